// round 12
// baseline (speedup 1.0000x reference)
#include <cuda_runtime.h>
#include <cuda.h>
#include <cuda_bf16.h>
#include <cuda_fp16.h>
#include <math.h>
#include <stdint.h>

// ============================================================================
// Attention-LSTM decoder. B=64, T_out=31, T_in=60, U=512, EMB=300, VOCAB=34004.
// Launch order (ncu captures app launch #4):
//   1 gather_emb   2 mega_convert (all weight converts + memory->fp16)
//   3 gemm3 (keys[fp16] + zpre + wbig[fused +Uk + gate-interleave])
//   4 step_loop (PERSISTENT, 64 CTAs, gates BK=128 3-stage | attention fp16)
//   5 states GEMM   6 vocab GEMM (1-term fp16)
// ============================================================================

#define B64   64
#define TOUT  31
#define TIN   60
#define UNITS 512
#define EMB   300
#define EMBP  320
#define VOCAB 34004
#define ROWS  (B64 * TOUT)     // 1984
#define MPAD  2048
#define VPAD  34048            // 266 * 128
#define HLD   (TOUT * 1024)

// ---------------- scratch ----------------------------------------------------
__device__ float g_embA  [ROWS * EMBP];
__device__ float g_zpre  [ROWS * 4 * UNITS];
__device__ float g_cbuf  [2][B64 * UNITS];
__device__ float g_hctx  [ROWS * 1024];
__device__ __align__(16) __half g_keysh[B64 * TIN * UNITS];      // fp16 keys
__device__ __align__(16) __half g_memh [B64 * TIN * UNITS];      // fp16 memory
__device__ __align__(16) __half g_wqKh [UNITS * UNITS];          // Wq [k][n] fp16
__device__ __align__(16) __half g_sA_h[MPAD * UNITS];            // pad rows stay 0
__device__ __align__(16) __half g_wT_h [(size_t)VPAD * UNITS];   // fp16 [n][k]
__device__ __align__(16) __nv_bfloat16 g_wkuH[2048 * 1024];      // [n'][k]
__device__ __align__(16) __nv_bfloat16 g_wkuL[2048 * 1024];
__device__ __align__(16) __nv_bfloat16 g_uk0H[2048 * 512];
__device__ __align__(16) __nv_bfloat16 g_uk0L[2048 * 512];
__device__ __align__(16) __nv_bfloat16 g_wmT_h [512 * 512];
__device__ __align__(16) __nv_bfloat16 g_wmT_l [512 * 512];
__device__ __align__(16) __nv_bfloat16 g_wk0T_h[2048 * EMBP];
__device__ __align__(16) __nv_bfloat16 g_wk0T_l[2048 * EMBP];
__device__ __align__(16) __nv_bfloat16 g_wkpT_h[2048 * 512];
__device__ __align__(16) __nv_bfloat16 g_wkpT_l[2048 * 512];
__device__ __align__(16) __nv_bfloat16 g_waT_h [512 * 1024];
__device__ __align__(16) __nv_bfloat16 g_waT_l [512 * 1024];

__device__ int g_bar_cnt = 0;
__device__ volatile unsigned g_bar_gen = 0;

// ---------------- PTX helpers -------------------------------------------------
__device__ __forceinline__ uint32_t smem_u32(const void* p) {
    uint32_t a;
    asm("{ .reg .u64 t; cvta.to.shared.u64 t, %1; cvt.u32.u64 %0, t; }" : "=r"(a) : "l"(p));
    return a;
}
__device__ __forceinline__ void ldm_x4(uint32_t& r0, uint32_t& r1, uint32_t& r2,
                                       uint32_t& r3, uint32_t addr) {
    asm volatile("ldmatrix.sync.aligned.m8n8.x4.shared.b16 {%0,%1,%2,%3}, [%4];"
                 : "=r"(r0), "=r"(r1), "=r"(r2), "=r"(r3) : "r"(addr));
}
__device__ __forceinline__ void ldm_x2(uint32_t& r0, uint32_t& r1, uint32_t addr) {
    asm volatile("ldmatrix.sync.aligned.m8n8.x2.shared.b16 {%0,%1}, [%2];"
                 : "=r"(r0), "=r"(r1) : "r"(addr));
}
__device__ __forceinline__ void mma_bf16(float* c, const uint32_t* a, const uint32_t* b) {
    asm volatile("mma.sync.aligned.m16n8k16.row.col.f32.bf16.bf16.f32 "
                 "{%0,%1,%2,%3}, {%4,%5,%6,%7}, {%8,%9}, {%0,%1,%2,%3};"
                 : "+f"(c[0]), "+f"(c[1]), "+f"(c[2]), "+f"(c[3])
                 : "r"(a[0]), "r"(a[1]), "r"(a[2]), "r"(a[3]), "r"(b[0]), "r"(b[1]));
}
__device__ __forceinline__ void mma_f16(float* c, const uint32_t* a, const uint32_t* b) {
    asm volatile("mma.sync.aligned.m16n8k16.row.col.f32.f16.f16.f32 "
                 "{%0,%1,%2,%3}, {%4,%5,%6,%7}, {%8,%9}, {%0,%1,%2,%3};"
                 : "+f"(c[0]), "+f"(c[1]), "+f"(c[2]), "+f"(c[3])
                 : "r"(a[0]), "r"(a[1]), "r"(a[2]), "r"(a[3]), "r"(b[0]), "r"(b[1]));
}
__device__ __forceinline__ void cp_async16(uint32_t dst, const void* src) {
    asm volatile("cp.async.cg.shared.global [%0], [%1], 16;" :: "r"(dst), "l"(src));
}
__device__ __forceinline__ void cp_commit() { asm volatile("cp.async.commit_group;"); }
template<int N> __device__ __forceinline__ void cp_wait() {
    asm volatile("cp.async.wait_group %0;" :: "n"(N));
}
__device__ __forceinline__ uint32_t pack_bf2(float a, float b) {
    __nv_bfloat162 t = __floats2bfloat162_rn(a, b);
    return *reinterpret_cast<uint32_t*>(&t);
}
__device__ __forceinline__ float bf_res(float a) {
    return a - __bfloat162float(__float2bfloat16(a));
}
__device__ __forceinline__ float fast_tanh(float x) {
    float e = __expf(2.f * x);
    return 1.f - __fdividef(2.f, e + 1.f);
}
__device__ __forceinline__ float fast_sigmoid(float x) {
    return __fdividef(1.f, 1.f + __expf(-x));
}
__device__ __forceinline__ void grid_barrier(int nCTA) {
    __syncthreads();
    if (threadIdx.x == 0) {
        unsigned gen = g_bar_gen;
        __threadfence();
        if (atomicAdd(&g_bar_cnt, 1) == nCTA - 1) {
            g_bar_cnt = 0;
            __threadfence();
            g_bar_gen = gen + 1;
        } else {
            while (g_bar_gen == gen) { }
        }
        __threadfence();
    }
    __syncthreads();
}

// ---------------------------------------------------------------------------
__global__ void gather_emb_kernel(const int* __restrict__ dec,
                                  const float* __restrict__ emb,
                                  float* __restrict__ out) {
    int r = blockIdx.x;          // r = t*64 + b
    int t = r >> 6, b = r & 63;
    int tok = dec[b * TOUT + t];
    const float* src = emb + (size_t)tok * EMB;
    float* dst = out + (size_t)r * EMBP;
    for (int e = threadIdx.x; e < EMBP; e += blockDim.x)
        dst[e] = (e < EMB) ? src[e] : 0.f;
}

// ---------------------------------------------------------------------------
// mega_convert: all one-time conversions (dispatch by blockIdx).
//  P0 [0,256)       : Wm -> wmT hi/lo
//  P1 [256,896)     : Wk[0:300] -> wk0T hi/lo
//  P2 [896,1920)    : Wk[300:812] -> wkpT hi/lo
//  P3 [1920,2176)   : Wq -> wqKh fp16 copy ([k][n])
//  P4 [2176,3200)   : Uk -> uk0 gate-interleaved hi/lo
//  P5 [3200,3712)   : Wa -> waT hi/lo
//  P6 [3712,20736)  : Wfc -> wT_h fp16 [n][k]
//  P7 [20736,22656) : memory -> memh fp16 copy
__global__ void mega_convert_kernel(const float* __restrict__ Wm,
                                    const float* __restrict__ Wk,
                                    const float* __restrict__ Uk,
                                    const float* __restrict__ Wq,
                                    const float* __restrict__ Wa,
                                    const float* __restrict__ Wfc,
                                    const float* __restrict__ mem,
                                    __nv_bfloat16* __restrict__ wmT_h,
                                    __nv_bfloat16* __restrict__ wmT_l,
                                    __nv_bfloat16* __restrict__ wk0T_h,
                                    __nv_bfloat16* __restrict__ wk0T_l,
                                    __nv_bfloat16* __restrict__ wkpT_h,
                                    __nv_bfloat16* __restrict__ wkpT_l,
                                    __half* __restrict__ wqKh,
                                    __nv_bfloat16* __restrict__ uk0H,
                                    __nv_bfloat16* __restrict__ uk0L,
                                    __nv_bfloat16* __restrict__ waT_h,
                                    __nv_bfloat16* __restrict__ waT_l,
                                    __half* __restrict__ wT_h,
                                    __half* __restrict__ memh)
{
    __shared__ float tile[32][33];
    int bid = blockIdx.x;
    int tx = threadIdx.x & 31, ty = threadIdx.x >> 5;

    if (bid >= 20736) {                  // P7: memory fp16 copy
        int base = (bid - 20736) * 1024;
        for (int e = threadIdx.x; e < 1024; e += 256)
            memh[base + e] = __float2half_rn(mem[base + e]);
        return;
    }
    if (bid >= 1920 && bid < 2176) {     // P3: Wq fp16 copy
        int base = (bid - 1920) * 1024;
        for (int e = threadIdx.x; e < 1024; e += 256)
            wqKh[base + e] = __float2half_rn(Wq[base + e]);
        return;
    }
    if (bid >= 3712) {                   // P6: Wfc fp16 transpose
        int i = bid - 3712;
        int n0 = (i % 1064) * 32, k0 = (i / 1064) * 32;
        for (int j = ty; j < 32; j += 8) {
            int n = n0 + tx;
            tile[j][tx] = (n < VOCAB) ? Wfc[(size_t)(k0 + j) * VOCAB + n] : 0.f;
        }
        __syncthreads();
        for (int j = ty; j < 32; j += 8)
            wT_h[(size_t)(n0 + j) * UNITS + k0 + tx] = __float2half_rn(tile[tx][j]);
        return;
    }

    const float* W; int K, N, ldn, Kpad, mode, n0, k0;
    __nv_bfloat16 *hi, *lo;
    if (bid < 256) {
        int i = bid; W = Wm; K = 512; N = 512; ldn = 512; Kpad = 512; mode = 0;
        hi = wmT_h; lo = wmT_l; n0 = (i % 16) * 32; k0 = (i / 16) * 32;
    } else if (bid < 896) {
        int i = bid - 256; W = Wk; K = EMB; N = 2048; ldn = 2048; Kpad = EMBP; mode = 0;
        hi = wk0T_h; lo = wk0T_l; n0 = (i % 64) * 32; k0 = (i / 64) * 32;
    } else if (bid < 1920) {
        int i = bid - 896; W = Wk + (size_t)EMB * 2048; K = 512; N = 2048;
        ldn = 2048; Kpad = 512; mode = 0;
        hi = wkpT_h; lo = wkpT_l; n0 = (i % 64) * 32; k0 = (i / 64) * 32;
    } else if (bid < 3200) {
        int i = bid - 2176; W = Uk; K = 512; N = 2048; ldn = 2048; Kpad = 512; mode = 2;
        hi = uk0H; lo = uk0L; n0 = (i % 64) * 32; k0 = (i / 64) * 32;
    } else {
        int i = bid - 3200; W = Wa; K = 1024; N = 512; ldn = 512; Kpad = 1024; mode = 0;
        hi = waT_h; lo = waT_l; n0 = (i % 16) * 32; k0 = (i / 16) * 32;
    }

    for (int j = ty; j < 32; j += 8) {
        int k = k0 + j, n = n0 + tx;
        tile[j][tx] = (k < K && n < N) ? W[(size_t)k * ldn + n] : 0.f;
    }
    __syncthreads();
    for (int j = ty; j < 32; j += 8) {
        int n = n0 + j, k = k0 + tx;
        float v = tile[tx][j];
        int nn = (mode == 2) ? ((n & 511) * 4 + (n >> 9)) : n;
        __nv_bfloat16 h = __float2bfloat16(v);
        hi[(size_t)nn * Kpad + k] = h;
        lo[(size_t)nn * Kpad + k] = __float2bfloat16(v - __bfloat162float(h));
    }
}

// ---------------------------------------------------------------------------
// Core split-bf16 3-term mma GEMM (fp32 A on the fly, pre-split B).
#define FTS     72
#define F_ARR   (128 * FTS * 2)
#define F_STAGE (4 * F_ARR)
#define F_SMEM  (2 * F_STAGE)

template<int MODE>
__device__ __forceinline__ void gemm_core(
    char* dsm, int m0, int n0,
    const float* __restrict__ A, int lda, int M, int N, int K,
    const __nv_bfloat16* __restrict__ BhT,
    const __nv_bfloat16* __restrict__ BlT,
    const float* __restrict__ bias,
    float* __restrict__ C, int ldc,
    __half* __restrict__ Ch,
    __nv_bfloat16* __restrict__ OH, __nv_bfloat16* __restrict__ OL)
{
    const int tid  = threadIdx.x;
    const int wid  = tid >> 5, lane = tid & 31;
    const int wm   = wid & 1,  wn   = wid >> 1;
    const int mbase = wm * 64, nbase = wn * 32;
    const uint32_t sb = smem_u32(dsm);
    const int NIT = K >> 6;

    float acc[16][4];
#pragma unroll
    for (int i = 0; i < 16; i++)
#pragma unroll
        for (int j = 0; j < 4; j++) acc[i][j] = 0.f;

    float4 Areg[8];
    auto loadA = [&](int it) {
        int koff = it * 64;
#pragma unroll
        for (int l = 0; l < 8; l++) {
            int q = tid + l * 256;
            int r = q >> 4, c4 = (q & 15) * 4;
            int gm = m0 + r;
            Areg[l] = (gm < M) ? *(const float4*)(A + (size_t)gm * lda + koff + c4)
                               : make_float4(0.f, 0.f, 0.f, 0.f);
        }
    };
    auto storeA = [&](int stage) {
#pragma unroll
        for (int l = 0; l < 8; l++) {
            int q = tid + l * 256;
            int r = q >> 4, c4 = (q & 15) * 4;
            float4 v = Areg[l];
            uint32_t off = (uint32_t)(r * FTS + c4) * 2;
            uint2 hi = make_uint2(pack_bf2(v.x, v.y), pack_bf2(v.z, v.w));
            uint2 lo = make_uint2(pack_bf2(bf_res(v.x), bf_res(v.y)),
                                  pack_bf2(bf_res(v.z), bf_res(v.w)));
            *(uint2*)(dsm + stage * F_STAGE + 0 * F_ARR + off) = hi;
            *(uint2*)(dsm + stage * F_STAGE + 1 * F_ARR + off) = lo;
        }
    };
    auto issueB = [&](int it, int stage) {
        int koff = it * 64;
#pragma unroll
        for (int arr = 0; arr < 2; arr++) {
            const __nv_bfloat16* src = arr ? BlT : BhT;
#pragma unroll
            for (int l = 0; l < 4; l++) {
                int q = tid + l * 256;
                int r = q >> 3, c8 = (q & 7) * 8;
                uint32_t dst = sb + stage * F_STAGE + (2 + arr) * F_ARR
                             + (uint32_t)(r * FTS + c8) * 2;
                cp_async16(dst, src + (size_t)(n0 + r) * K + koff + c8);
            }
        }
        cp_commit();
    };
    auto compute = [&](int stage) {
        uint32_t aHb = sb + stage * F_STAGE;
        uint32_t aLb = aHb + F_ARR;
        uint32_t bHb = aHb + 2 * F_ARR;
        uint32_t bLb = aHb + 3 * F_ARR;
#pragma unroll
        for (int ks = 0; ks < 4; ks++) {
            uint32_t a_off = (uint32_t)(((mbase + (lane & 15)) * FTS
                              + ks * 16 + (lane >> 4) * 8) * 2);
            uint32_t aH[4][4], aL[4][4];
#pragma unroll
            for (int i = 0; i < 4; i++) {
                uint32_t o = a_off + (uint32_t)(i * 16 * FTS * 2);
                ldm_x4(aH[i][0], aH[i][1], aH[i][2], aH[i][3], aHb + o);
                ldm_x4(aL[i][0], aL[i][1], aL[i][2], aL[i][3], aLb + o);
            }
            uint32_t b_off = (uint32_t)(((nbase + (lane & 7) + (lane >> 4) * 8) * FTS
                              + ks * 16 + ((lane >> 3) & 1) * 8) * 2);
            uint32_t bH[4][2], bL[4][2];
#pragma unroll
            for (int jp = 0; jp < 2; jp++) {
                uint32_t o = b_off + (uint32_t)(jp * 16 * FTS * 2);
                ldm_x4(bH[jp*2][0], bH[jp*2][1], bH[jp*2+1][0], bH[jp*2+1][1], bHb + o);
                ldm_x4(bL[jp*2][0], bL[jp*2][1], bL[jp*2+1][0], bL[jp*2+1][1], bLb + o);
            }
#pragma unroll
            for (int i = 0; i < 4; i++)
#pragma unroll
                for (int j = 0; j < 4; j++) {
                    mma_bf16(acc[i * 4 + j], aH[i], bH[j]);
                    mma_bf16(acc[i * 4 + j], aH[i], bL[j]);
                    mma_bf16(acc[i * 4 + j], aL[i], bH[j]);
                }
        }
    };

    loadA(0);
    issueB(0, 0);
    if (NIT > 1) issueB(1, 1);
    for (int it = 0; it < NIT; it++) {
        int stage = it & 1;
        if (it >= NIT - 2) cp_wait<0>(); else cp_wait<1>();
        storeA(stage);
        __syncthreads();
        if (it + 1 < NIT) loadA(it + 1);
        compute(stage);
        __syncthreads();
        if (it + 2 < NIT) issueB(it + 2, stage);
    }

#pragma unroll
    for (int i = 0; i < 4; i++) {
        int row0 = m0 + mbase + i * 16 + (lane >> 2);
#pragma unroll
        for (int j = 0; j < 4; j++) {
            int col = n0 + nbase + j * 8 + (lane & 3) * 2;
            if (col >= N) continue;
            const float* c = acc[i * 4 + j];
#pragma unroll
            for (int hrow = 0; hrow < 2; hrow++) {
                int gm = row0 + hrow * 8;
                if (gm >= M) continue;
                float v0 = c[hrow * 2 + 0], v1 = c[hrow * 2 + 1];
                if (MODE == 0) {
                    float b0 = bias ? bias[col] : 0.f;
                    float b1 = bias ? bias[col + 1] : 0.f;
                    C[(size_t)gm * ldc + col]     = v0 + b0;
                    C[(size_t)gm * ldc + col + 1] = v1 + b1;
                } else if (MODE == 1) {
                    Ch[(size_t)gm * ldc + col]     = __float2half_rn(v0);
                    Ch[(size_t)gm * ldc + col + 1] = __float2half_rn(v1);
                } else {   // MODE 3
                    if (gm < 512) {
                        v0 += bias[(size_t)gm * 2048 + col];
                        v1 += bias[(size_t)gm * 2048 + col + 1];
                    }
                    int np0 = (col & 511) * 4 + (col >> 9);
                    int np1 = ((col + 1) & 511) * 4 + ((col + 1) >> 9);
                    __nv_bfloat16 h0 = __float2bfloat16(v0);
                    __nv_bfloat16 h1 = __float2bfloat16(v1);
                    OH[(size_t)np0 * 1024 + gm] = h0;
                    OL[(size_t)np0 * 1024 + gm] =
                        __float2bfloat16(v0 - __bfloat162float(h0));
                    OH[(size_t)np1 * 1024 + gm] = h1;
                    OL[(size_t)np1 * 1024 + gm] =
                        __float2bfloat16(v1 - __bfloat162float(h1));
                }
            }
        }
    }
}

// gemm3: keys->fp16 (120) + zpre (256) + wbig (128) in one launch.
__global__ void __launch_bounds__(256)
gemm3_kernel(const float* __restrict__ mem,
             const __nv_bfloat16* __restrict__ wmT_h,
             const __nv_bfloat16* __restrict__ wmT_l,
             __half* __restrict__ keysh,
             const float* __restrict__ embA,
             const __nv_bfloat16* __restrict__ wk0T_h,
             const __nv_bfloat16* __restrict__ wk0T_l,
             const float* __restrict__ bk,
             float* __restrict__ zpre,
             const float* __restrict__ Wa,
             const __nv_bfloat16* __restrict__ wkpT_h,
             const __nv_bfloat16* __restrict__ wkpT_l,
             const float* __restrict__ Uk,
             __nv_bfloat16* __restrict__ wkuH,
             __nv_bfloat16* __restrict__ wkuL)
{
    extern __shared__ char dsm[];
    int bid = blockIdx.x;
    if (bid < 120) {
        int m0 = (bid % 30) * 128, n0 = (bid / 30) * 128;
        gemm_core<1>(dsm, m0, n0, mem, UNITS, B64 * TIN, UNITS, UNITS,
                     wmT_h, wmT_l, nullptr, nullptr, UNITS, keysh,
                     nullptr, nullptr);
    } else if (bid < 376) {
        int p = bid - 120;
        int m0 = (p % 16) * 128, n0 = (p / 16) * 128;
        gemm_core<0>(dsm, m0, n0, embA, EMBP, ROWS, 2048, EMBP,
                     wk0T_h, wk0T_l, bk, zpre, 2048, nullptr,
                     nullptr, nullptr);
    } else {
        int p = bid - 376;
        int m0 = (p % 8) * 128, n0 = (p / 8) * 128;
        gemm_core<3>(dsm, m0, n0, Wa, UNITS, 1024, 2048, UNITS,
                     wkpT_h, wkpT_l, Uk, nullptr, 0, nullptr,
                     wkuH, wkuL);
    }
}

__global__ void __launch_bounds__(256)
gemm_states_kernel(const float* __restrict__ hctx,
                   const __nv_bfloat16* __restrict__ waT_h,
                   const __nv_bfloat16* __restrict__ waT_l,
                   __half* __restrict__ sA_h)
{
    extern __shared__ char dsm[];
    int m0 = blockIdx.x * 128, n0 = blockIdx.y * 128;
    gemm_core<1>(dsm, m0, n0, hctx, 1024, ROWS, UNITS, 1024,
                 waT_h, waT_l, nullptr, nullptr, UNITS, sA_h,
                 nullptr, nullptr);
}

// ---------------------------------------------------------------------------
// PERSISTENT step loop: 64 CTAs x 512 threads.
// Gates: tile 64m x 32n' (n' = cta*32..+31), BK=128, 3-stage cp.async,
// 16 mma warps of 16x8. Fused LSTM. Attention: CTA b = cta (all 64).
#define PTS     136                        // 128 + 8 pad (halfs per row)
#define P_AH    0
#define P_AL    17408                      // 64*136*2
#define P_BH    34816
#define P_BL    43520                      // +32*136*2
#define P_STAGE 52224
#define P_SMEM  (3 * P_STAGE)              // 156672 B

__global__ void __launch_bounds__(512, 1)
step_loop_kernel(const float* __restrict__ h0,
                 const float* __restrict__ c0,
                 const __nv_bfloat16* __restrict__ uk0H,
                 const __nv_bfloat16* __restrict__ uk0L,
                 const __nv_bfloat16* __restrict__ wkuH,
                 const __nv_bfloat16* __restrict__ wkuL,
                 const float* __restrict__ zpre,
                 float* __restrict__ cbuf,
                 float* __restrict__ hctx,
                 const __half* __restrict__ wqKh,   // [k][n]
                 const __half* __restrict__ keysh,
                 const __half* __restrict__ memh,
                 const float* __restrict__ v_att)
{
    extern __shared__ char dsm[];
    const int cta  = blockIdx.x;              // 0..63
    const int tid  = threadIdx.x;
    const int wid  = tid >> 5, lane = tid & 31;
    const int mbase = (wid & 3) * 16;          // 4 m-groups
    const int nbase = (wid >> 2) * 8;          // 4 n-groups (32 n' total)
    const int n0   = cta * 32;
    const uint32_t sb = smem_u32(dsm);
    const int nCTA = gridDim.x;

    for (int t = 0; t < TOUT; t++) {
        // ================= gates phase =================
        const float* Aptr; int astride, K;
        const __nv_bfloat16 *BH, *BL;
        if (t == 0) { Aptr = h0; astride = UNITS; K = 512; BH = uk0H; BL = uk0L; }
        else { Aptr = hctx + (size_t)(t - 1) * 1024; astride = HLD; K = 1024;
               BH = wkuH; BL = wkuL; }
        const float* cprev = t ? (cbuf + (size_t)((t - 1) & 1) * B64 * UNITS) : c0;
        float* cnew = cbuf + (size_t)(t & 1) * B64 * UNITS;
        const int NIT = K >> 7;                // BK=128

        float acc[4] = {0.f, 0.f, 0.f, 0.f};
        float4 Areg[4];

        auto issueB = [&](int it, int stage) {
            int koff = it * 128;
            // 2 arrays x 32 rows x 128 halfs = 1024 x 16B chunks; 2/thread
#pragma unroll
            for (int l = 0; l < 2; l++) {
                int q = tid + l * 512;
                int arr = q >> 9;
                int rem = q & 511;
                int r   = rem >> 4;
                int c8  = (rem & 15) * 8;
                const __nv_bfloat16* src = arr ? BL : BH;
                uint32_t dst = sb + stage * P_STAGE + (arr ? P_BL : P_BH)
                             + (uint32_t)(r * PTS + c8) * 2;
                cp_async16(dst, src + (size_t)(n0 + r) * K + koff + c8);
            }
            cp_commit();
        };
        auto loadA = [&](int it) {
            int koff = it * 128;
#pragma unroll
            for (int l = 0; l < 4; l++) {
                int q = tid + l * 512;         // 2048 float4 (64 x 32)
                int r = q >> 5, c4 = (q & 31) * 4;
                Areg[l] = *(const float4*)(Aptr + (size_t)r * astride + koff + c4);
            }
        };
        auto storeA = [&](int stage) {
#pragma unroll
            for (int l = 0; l < 4; l++) {
                int q = tid + l * 512;
                int r = q >> 5, c4 = (q & 31) * 4;
                float4 v = Areg[l];
                uint32_t off = (uint32_t)(r * PTS + c4) * 2;
                uint2 hi = make_uint2(pack_bf2(v.x, v.y), pack_bf2(v.z, v.w));
                uint2 lo = make_uint2(pack_bf2(bf_res(v.x), bf_res(v.y)),
                                      pack_bf2(bf_res(v.z), bf_res(v.w)));
                *(uint2*)(dsm + stage * P_STAGE + P_AH + off) = hi;
                *(uint2*)(dsm + stage * P_STAGE + P_AL + off) = lo;
            }
        };
        auto compute = [&](int stage) {
            uint32_t aHb = sb + stage * P_STAGE + P_AH;
            uint32_t aLb = sb + stage * P_STAGE + P_AL;
            uint32_t bHb = sb + stage * P_STAGE + P_BH;
            uint32_t bLb = sb + stage * P_STAGE + P_BL;
#pragma unroll
            for (int ks = 0; ks < 8; ks++) {
                uint32_t a_off = (uint32_t)(((mbase + (lane & 15)) * PTS
                                  + ks * 16 + (lane >> 4) * 8) * 2);
                uint32_t aH[4], aL[4];
                ldm_x4(aH[0], aH[1], aH[2], aH[3], aHb + a_off);
                ldm_x4(aL[0], aL[1], aL[2], aL[3], aLb + a_off);
                uint32_t b_off = (uint32_t)(((nbase + (lane & 7)) * PTS
                                  + ks * 16 + ((lane >> 3) & 1) * 8) * 2);
                uint32_t bH[2], bL[2];
                ldm_x2(bH[0], bH[1], bHb + b_off);
                ldm_x2(bL[0], bL[1], bLb + b_off);
                mma_bf16(acc, aH, bH);
                mma_bf16(acc, aH, bL);
                mma_bf16(acc, aL, bH);
            }
        };

        loadA(0);
        issueB(0, 0);
        if (NIT > 1) issueB(1, 1);
        if (NIT > 2) issueB(2, 2);
        for (int it = 0; it < NIT; it++) {
            int stage = it % 3;
            if (it + 3 <= NIT)      cp_wait<2>();
            else if (it + 2 == NIT) cp_wait<1>();
            else                    cp_wait<0>();
            storeA(stage);
            __syncthreads();
            if (it + 1 < NIT) loadA(it + 1);
            compute(stage);
            __syncthreads();
            if (it + 3 < NIT) issueB(it + 3, stage);
        }

        // ---- LSTM epilogue ----
        float* zbuf = (float*)dsm;                 // [64][36]
        {
            int row = mbase + (lane >> 2);
            int col = nbase + (lane & 3) * 2;
            zbuf[row * 36 + col]           = acc[0];
            zbuf[row * 36 + col + 1]       = acc[1];
            zbuf[(row + 8) * 36 + col]     = acc[2];
            zbuf[(row + 8) * 36 + col + 1] = acc[3];
        }
        __syncthreads();
        {
            int b  = tid >> 3, ul = tid & 7;       // 64 b x 8 u
            int u  = cta * 8 + ul;
            const float* ad = zpre + (size_t)t * B64 * 2048 + (size_t)b * 2048;
            float zi = zbuf[b * 36 + ul * 4 + 0] + ad[u];
            float zf = zbuf[b * 36 + ul * 4 + 1] + ad[512 + u];
            float zg = zbuf[b * 36 + ul * 4 + 2] + ad[1024 + u];
            float zo = zbuf[b * 36 + ul * 4 + 3] + ad[1536 + u];
            float si = fast_sigmoid(zi);
            float sf = fast_sigmoid(zf);
            float so = fast_sigmoid(zo);
            float tg = fast_tanh(zg);
            float c  = sf * cprev[(size_t)b * UNITS + u] + si * tg;
            float h  = so * fast_tanh(c);
            cnew[(size_t)b * UNITS + u] = c;
            hctx[(size_t)b * HLD + (size_t)t * 1024 + u] = h;
        }

        grid_barrier(nCTA);

        // ================= attention phase =================
        {
            int b = cta;
            float* sh  = (float*)dsm;
            float* sq  = sh + 512;
            float* ssc = sq + 512;
            float* hrow = hctx + (size_t)b * HLD + (size_t)t * 1024;

            sh[tid] = hrow[tid];
            __syncthreads();
            {   // q[n] = sum_k h[k] * Wq[k][n]; coalesced k-major
                float a0 = 0.f, a1 = 0.f, a2 = 0.f, a3 = 0.f;
#pragma unroll 4
                for (int k = 0; k < UNITS; k += 4) {
                    a0 = fmaf(sh[k + 0], __half2float(wqKh[(size_t)(k + 0) * UNITS + tid]), a0);
                    a1 = fmaf(sh[k + 1], __half2float(wqKh[(size_t)(k + 1) * UNITS + tid]), a1);
                    a2 = fmaf(sh[k + 2], __half2float(wqKh[(size_t)(k + 2) * UNITS + tid]), a2);
                    a3 = fmaf(sh[k + 3], __half2float(wqKh[(size_t)(k + 3) * UNITS + tid]), a3);
                }
                sq[tid] = (a0 + a1) + (a2 + a3);
            }
            __syncthreads();

            for (int s = wid; s < TIN; s += 16) {
                const __half* krow = keysh + ((size_t)b * TIN + s) * UNITS;
                float sc = 0.f;
#pragma unroll 4
                for (int u = lane; u < UNITS; u += 32)
                    sc += fast_tanh(__half2float(krow[u]) + sq[u]) * v_att[u];
#pragma unroll
                for (int off = 16; off; off >>= 1)
                    sc += __shfl_xor_sync(~0u, sc, off);
                if (lane == 0) ssc[s] = sc;
            }
            __syncthreads();

            if (tid < 32) {
                float m = -1e30f;
                for (int s = lane; s < TIN; s += 32) m = fmaxf(m, ssc[s]);
#pragma unroll
                for (int off = 16; off; off >>= 1)
                    m = fmaxf(m, __shfl_xor_sync(~0u, m, off));
                float ssum = 0.f;
                for (int s = lane; s < TIN; s += 32) {
                    float e = __expf(ssc[s] - m);
                    ssc[s] = e; ssum += e;
                }
#pragma unroll
                for (int off = 16; off; off >>= 1)
                    ssum += __shfl_xor_sync(~0u, ssum, off);
                float inv = __fdividef(1.f, ssum);
                for (int s = lane; s < TIN; s += 32) ssc[s] *= inv;
            }
            __syncthreads();

            const __half* mrow = memh + (size_t)b * TIN * UNITS;
            float accc = 0.f;
#pragma unroll 4
            for (int s = 0; s < TIN; s++)
                accc = fmaf(ssc[s], __half2float(mrow[(size_t)s * UNITS + tid]), accc);
            hrow[512 + tid] = accc;
        }

        grid_barrier(nCTA);
    }
}

// ---------------------------------------------------------------------------
// Vocab GEMM: 1-term fp16.
#define V_ARR   (128 * FTS * 2)
#define V_STAGE (2 * V_ARR)
#define V_SMEM  (2 * V_STAGE)

__global__ void __launch_bounds__(256)
gemm_vocab_f16(const __half* __restrict__ Ah,
               const __half* __restrict__ Bh,
               const float* __restrict__ bias,
               float* __restrict__ out)
{
    extern __shared__ char dsm[];
    const int m0 = blockIdx.x * 128;
    const int n0 = blockIdx.y * 128;
    const int tid  = threadIdx.x;
    const int wid  = tid >> 5, lane = tid & 31;
    const int wm   = wid & 1,  wn   = wid >> 1;
    const int mbase = wm * 64, nbase = wn * 32;
    const uint32_t sb = smem_u32(dsm);

    float acc[16][4];
#pragma unroll
    for (int i = 0; i < 16; i++)
#pragma unroll
        for (int j = 0; j < 4; j++) acc[i][j] = 0.f;

    auto issue = [&](int it, int stage) {
        int koff = it * 64;
#pragma unroll
        for (int arr = 0; arr < 2; arr++) {
            const __half* src = arr ? Bh : Ah;
            const int rbase = arr ? n0 : m0;
#pragma unroll
            for (int l = 0; l < 4; l++) {
                int q = tid + l * 256;
                int r = q >> 3, c8 = (q & 7) * 8;
                uint32_t dst = sb + stage * V_STAGE + arr * V_ARR
                             + (uint32_t)(r * FTS + c8) * 2;
                cp_async16(dst, src + (size_t)(rbase + r) * UNITS + koff + c8);
            }
        }
        cp_commit();
    };
    auto compute = [&](int stage) {
        uint32_t aHb = sb + stage * V_STAGE;
        uint32_t bHb = aHb + V_ARR;
#pragma unroll
        for (int ks = 0; ks < 4; ks++) {
            uint32_t a_off = (uint32_t)(((mbase + (lane & 15)) * FTS
                              + ks * 16 + (lane >> 4) * 8) * 2);
            uint32_t aH[4][4];
#pragma unroll
            for (int i = 0; i < 4; i++) {
                uint32_t o = a_off + (uint32_t)(i * 16 * FTS * 2);
                ldm_x4(aH[i][0], aH[i][1], aH[i][2], aH[i][3], aHb + o);
            }
            uint32_t b_off = (uint32_t)(((nbase + (lane & 7) + (lane >> 4) * 8) * FTS
                              + ks * 16 + ((lane >> 3) & 1) * 8) * 2);
            uint32_t bH[4][2];
#pragma unroll
            for (int jp = 0; jp < 2; jp++) {
                uint32_t o = b_off + (uint32_t)(jp * 16 * FTS * 2);
                ldm_x4(bH[jp*2][0], bH[jp*2][1], bH[jp*2+1][0], bH[jp*2+1][1], bHb + o);
            }
#pragma unroll
            for (int i = 0; i < 4; i++)
#pragma unroll
                for (int j = 0; j < 4; j++)
                    mma_f16(acc[i * 4 + j], aH[i], bH[j]);
        }
    };

    issue(0, 0);
    issue(1, 1);
    for (int it = 0; it < 8; it++) {
        int stage = it & 1;
        if (it >= 6) cp_wait<0>(); else cp_wait<1>();
        __syncthreads();
        compute(stage);
        __syncthreads();
        if (it + 2 < 8) issue(it + 2, stage);
    }

#pragma unroll
    for (int i = 0; i < 4; i++) {
        int row0 = m0 + mbase + i * 16 + (lane >> 2);
#pragma unroll
        for (int j = 0; j < 4; j++) {
            int col = n0 + nbase + j * 8 + (lane & 3) * 2;
            if (col >= VOCAB) continue;
            float b0 = bias[col], b1 = bias[col + 1];
            const float* c = acc[i * 4 + j];
            if (row0 < ROWS) {
                out[(size_t)row0 * VOCAB + col]     = c[0] + b0;
                out[(size_t)row0 * VOCAB + col + 1] = c[1] + b1;
            }
            if (row0 + 8 < ROWS) {
                out[(size_t)(row0 + 8) * VOCAB + col]     = c[2] + b0;
                out[(size_t)(row0 + 8) * VOCAB + col + 1] = c[3] + b1;
            }
        }
    }
}

// ---------------------------------------------------------------------------
static inline float* sym_addr(const void* sym) {
    void* p = nullptr;
    cudaGetSymbolAddress(&p, sym);
    return (float*)p;
}
static inline __nv_bfloat16* sym_addr_bf(const void* sym) {
    void* p = nullptr;
    cudaGetSymbolAddress(&p, sym);
    return (__nv_bfloat16*)p;
}
static inline __half* sym_addr_h(const void* sym) {
    void* p = nullptr;
    cudaGetSymbolAddress(&p, sym);
    return (__half*)p;
}

extern "C" void kernel_launch(void* const* d_in, const int* in_sizes, int n_in,
                              void* d_out, int out_size)
{
    const int*   dec = (const int*)  d_in[0];
    const float* h0  = (const float*)d_in[1];
    const float* c0  = (const float*)d_in[2];
    const float* mem = (const float*)d_in[3];
    const float* emb = (const float*)d_in[4];
    const float* Wk  = (const float*)d_in[5];
    const float* Uk  = (const float*)d_in[6];
    const float* bk  = (const float*)d_in[7];
    const float* Wm  = (const float*)d_in[8];
    const float* Wq  = (const float*)d_in[9];
    const float* vat = (const float*)d_in[10];
    const float* Wa  = (const float*)d_in[11];
    const float* Wfc = (const float*)d_in[12];
    const float* bfc = (const float*)d_in[13];
    float* out = (float*)d_out;

    float* embA   = sym_addr(g_embA);
    float* zpre   = sym_addr(g_zpre);
    float* cbuf   = sym_addr(g_cbuf);
    float* hctx   = sym_addr(g_hctx);
    __half* keysh = sym_addr_h(g_keysh);
    __half* memh  = sym_addr_h(g_memh);
    __half* wqKh  = sym_addr_h(g_wqKh);
    __half* sA_h  = sym_addr_h(g_sA_h);
    __half* wT_h  = sym_addr_h(g_wT_h);
    __nv_bfloat16* wkuH = sym_addr_bf(g_wkuH);
    __nv_bfloat16* wkuL = sym_addr_bf(g_wkuL);
    __nv_bfloat16* uk0H = sym_addr_bf(g_uk0H);
    __nv_bfloat16* uk0L = sym_addr_bf(g_uk0L);
    __nv_bfloat16* wmT_h  = sym_addr_bf(g_wmT_h);
    __nv_bfloat16* wmT_l  = sym_addr_bf(g_wmT_l);
    __nv_bfloat16* wk0T_h = sym_addr_bf(g_wk0T_h);
    __nv_bfloat16* wk0T_l = sym_addr_bf(g_wk0T_l);
    __nv_bfloat16* wkpT_h = sym_addr_bf(g_wkpT_h);
    __nv_bfloat16* wkpT_l = sym_addr_bf(g_wkpT_l);
    __nv_bfloat16* waT_h  = sym_addr_bf(g_waT_h);
    __nv_bfloat16* waT_l  = sym_addr_bf(g_waT_l);

    cudaFuncSetAttribute(gemm3_kernel,
                         cudaFuncAttributeMaxDynamicSharedMemorySize, F_SMEM);
    cudaFuncSetAttribute(gemm_states_kernel,
                         cudaFuncAttributeMaxDynamicSharedMemorySize, F_SMEM);
    cudaFuncSetAttribute(step_loop_kernel,
                         cudaFuncAttributeMaxDynamicSharedMemorySize, P_SMEM);
    cudaFuncSetAttribute(gemm_vocab_f16,
                         cudaFuncAttributeMaxDynamicSharedMemorySize, V_SMEM);

    // 1: gather
    gather_emb_kernel<<<ROWS, 128>>>(dec, emb, embA);
    // 2: all converts (weights + memory fp16)
    mega_convert_kernel<<<22656, 256>>>(Wm, Wk, Uk, Wq, Wa, Wfc, mem,
                                        wmT_h, wmT_l, wk0T_h, wk0T_l,
                                        wkpT_h, wkpT_l, wqKh, uk0H, uk0L,
                                        waT_h, waT_l, wT_h, memh);
    // 3: keys(fp16) + zpre + wbig
    gemm3_kernel<<<504, 256, F_SMEM>>>(mem, wmT_h, wmT_l, keysh,
                                       embA, wk0T_h, wk0T_l, bk, zpre,
                                       Wa, wkpT_h, wkpT_l, Uk, wkuH, wkuL);
    // 4: persistent step loop (64 CTAs)  <-- ncu capture target
    step_loop_kernel<<<64, 512, P_SMEM>>>(
        h0, c0, uk0H, uk0L, wkuH, wkuL, zpre, cbuf, hctx,
        wqKh, keysh, memh, vat);
    // 5: states = hctx @ Wa -> fp16
    gemm_states_kernel<<<dim3(16, 4), 256, F_SMEM>>>(hctx, waT_h, waT_l, sA_h);
    // 6: vocab projection
    gemm_vocab_f16<<<dim3(MPAD / 128, VPAD / 128), 256, V_SMEM>>>(
        sA_h, wT_h, bfc, out);
}

// round 13
// speedup vs baseline: 1.1394x; 1.1394x over previous
#include <cuda_runtime.h>
#include <cuda.h>
#include <cuda_bf16.h>
#include <cuda_fp16.h>
#include <math.h>
#include <stdint.h>

// ============================================================================
// Attention-LSTM decoder. B=64, T_out=31, T_in=60, U=512, EMB=300, VOCAB=34004.
// R11 structure (known-good 1554us) + vectorized q-GEMV (uint4 loads).
//   1 gather_emb   2 mega_convert   3 gemm3 (keys fp16 + zpre + wbig)
//   4 step_loop (PERSISTENT, 128 CTAs)   5 states GEMM   6 vocab GEMM
// ============================================================================

#define B64   64
#define TOUT  31
#define TIN   60
#define UNITS 512
#define EMB   300
#define EMBP  320
#define VOCAB 34004
#define ROWS  (B64 * TOUT)     // 1984
#define MPAD  2048
#define VPAD  34048            // 266 * 128
#define HLD   (TOUT * 1024)

// ---------------- scratch ----------------------------------------------------
__device__ float g_embA  [ROWS * EMBP];
__device__ float g_zpre  [ROWS * 4 * UNITS];
__device__ float g_cbuf  [2][B64 * UNITS];
__device__ float g_hctx  [ROWS * 1024];
__device__ __align__(16) __half g_keysh[B64 * TIN * UNITS];      // fp16 keys
__device__ __align__(16) __half g_wqKh [UNITS * UNITS];          // Wq [k][n] fp16
__device__ __align__(16) __half g_sA_h[MPAD * UNITS];            // pad rows stay 0
__device__ __align__(16) __half g_wT_h [(size_t)VPAD * UNITS];   // fp16 [n][k]
__device__ __align__(16) __nv_bfloat16 g_wkuH[2048 * 1024];      // [n'][k]
__device__ __align__(16) __nv_bfloat16 g_wkuL[2048 * 1024];
__device__ __align__(16) __nv_bfloat16 g_uk0H[2048 * 512];
__device__ __align__(16) __nv_bfloat16 g_uk0L[2048 * 512];
__device__ __align__(16) __nv_bfloat16 g_wmT_h [512 * 512];
__device__ __align__(16) __nv_bfloat16 g_wmT_l [512 * 512];
__device__ __align__(16) __nv_bfloat16 g_wk0T_h[2048 * EMBP];
__device__ __align__(16) __nv_bfloat16 g_wk0T_l[2048 * EMBP];
__device__ __align__(16) __nv_bfloat16 g_wkpT_h[2048 * 512];
__device__ __align__(16) __nv_bfloat16 g_wkpT_l[2048 * 512];
__device__ __align__(16) __nv_bfloat16 g_waT_h [512 * 1024];
__device__ __align__(16) __nv_bfloat16 g_waT_l [512 * 1024];

__device__ int g_bar_cnt = 0;
__device__ volatile unsigned g_bar_gen = 0;

// ---------------- PTX helpers -------------------------------------------------
__device__ __forceinline__ uint32_t smem_u32(const void* p) {
    uint32_t a;
    asm("{ .reg .u64 t; cvta.to.shared.u64 t, %1; cvt.u32.u64 %0, t; }" : "=r"(a) : "l"(p));
    return a;
}
__device__ __forceinline__ void ldm_x4(uint32_t& r0, uint32_t& r1, uint32_t& r2,
                                       uint32_t& r3, uint32_t addr) {
    asm volatile("ldmatrix.sync.aligned.m8n8.x4.shared.b16 {%0,%1,%2,%3}, [%4];"
                 : "=r"(r0), "=r"(r1), "=r"(r2), "=r"(r3) : "r"(addr));
}
__device__ __forceinline__ void ldm_x2(uint32_t& r0, uint32_t& r1, uint32_t addr) {
    asm volatile("ldmatrix.sync.aligned.m8n8.x2.shared.b16 {%0,%1}, [%2];"
                 : "=r"(r0), "=r"(r1) : "r"(addr));
}
__device__ __forceinline__ void mma_bf16(float* c, const uint32_t* a, const uint32_t* b) {
    asm volatile("mma.sync.aligned.m16n8k16.row.col.f32.bf16.bf16.f32 "
                 "{%0,%1,%2,%3}, {%4,%5,%6,%7}, {%8,%9}, {%0,%1,%2,%3};"
                 : "+f"(c[0]), "+f"(c[1]), "+f"(c[2]), "+f"(c[3])
                 : "r"(a[0]), "r"(a[1]), "r"(a[2]), "r"(a[3]), "r"(b[0]), "r"(b[1]));
}
__device__ __forceinline__ void mma_f16(float* c, const uint32_t* a, const uint32_t* b) {
    asm volatile("mma.sync.aligned.m16n8k16.row.col.f32.f16.f16.f32 "
                 "{%0,%1,%2,%3}, {%4,%5,%6,%7}, {%8,%9}, {%0,%1,%2,%3};"
                 : "+f"(c[0]), "+f"(c[1]), "+f"(c[2]), "+f"(c[3])
                 : "r"(a[0]), "r"(a[1]), "r"(a[2]), "r"(a[3]), "r"(b[0]), "r"(b[1]));
}
__device__ __forceinline__ void cp_async16(uint32_t dst, const void* src) {
    asm volatile("cp.async.cg.shared.global [%0], [%1], 16;" :: "r"(dst), "l"(src));
}
__device__ __forceinline__ void cp_commit() { asm volatile("cp.async.commit_group;"); }
template<int N> __device__ __forceinline__ void cp_wait() {
    asm volatile("cp.async.wait_group %0;" :: "n"(N));
}
__device__ __forceinline__ uint32_t pack_bf2(float a, float b) {
    __nv_bfloat162 t = __floats2bfloat162_rn(a, b);
    return *reinterpret_cast<uint32_t*>(&t);
}
__device__ __forceinline__ float bf_res(float a) {
    return a - __bfloat162float(__float2bfloat16(a));
}
__device__ __forceinline__ float fast_tanh(float x) {
    float e = __expf(2.f * x);
    return 1.f - __fdividef(2.f, e + 1.f);
}
__device__ __forceinline__ float fast_sigmoid(float x) {
    return __fdividef(1.f, 1.f + __expf(-x));
}
__device__ __forceinline__ void grid_barrier(int nCTA) {
    __syncthreads();
    if (threadIdx.x == 0) {
        unsigned gen = g_bar_gen;
        __threadfence();
        if (atomicAdd(&g_bar_cnt, 1) == nCTA - 1) {
            g_bar_cnt = 0;
            __threadfence();
            g_bar_gen = gen + 1;
        } else {
            while (g_bar_gen == gen) { }
        }
        __threadfence();
    }
    __syncthreads();
}

// ---------------------------------------------------------------------------
__global__ void gather_emb_kernel(const int* __restrict__ dec,
                                  const float* __restrict__ emb,
                                  float* __restrict__ out) {
    int r = blockIdx.x;          // r = t*64 + b
    int t = r >> 6, b = r & 63;
    int tok = dec[b * TOUT + t];
    const float* src = emb + (size_t)tok * EMB;
    float* dst = out + (size_t)r * EMBP;
    for (int e = threadIdx.x; e < EMBP; e += blockDim.x)
        dst[e] = (e < EMB) ? src[e] : 0.f;
}

// ---------------------------------------------------------------------------
// mega_convert (R11 layout):
//  P0 [0,256) Wm | P1 [256,896) Wk0 | P2 [896,1920) Wk' | P3 [1920,2176) Wq fp16
//  P4 [2176,3200) Uk interleaved | P5 [3200,3712) Wa | P6 [3712,20736) Wfc fp16
__global__ void mega_convert_kernel(const float* __restrict__ Wm,
                                    const float* __restrict__ Wk,
                                    const float* __restrict__ Uk,
                                    const float* __restrict__ Wq,
                                    const float* __restrict__ Wa,
                                    const float* __restrict__ Wfc,
                                    __nv_bfloat16* __restrict__ wmT_h,
                                    __nv_bfloat16* __restrict__ wmT_l,
                                    __nv_bfloat16* __restrict__ wk0T_h,
                                    __nv_bfloat16* __restrict__ wk0T_l,
                                    __nv_bfloat16* __restrict__ wkpT_h,
                                    __nv_bfloat16* __restrict__ wkpT_l,
                                    __half* __restrict__ wqKh,
                                    __nv_bfloat16* __restrict__ uk0H,
                                    __nv_bfloat16* __restrict__ uk0L,
                                    __nv_bfloat16* __restrict__ waT_h,
                                    __nv_bfloat16* __restrict__ waT_l,
                                    __half* __restrict__ wT_h)
{
    __shared__ float tile[32][33];
    int bid = blockIdx.x;
    int tx = threadIdx.x & 31, ty = threadIdx.x >> 5;

    if (bid >= 1920 && bid < 2176) {     // P3: Wq straight fp16 copy
        int base = (bid - 1920) * 1024;
        for (int e = threadIdx.x; e < 1024; e += 256)
            wqKh[base + e] = __float2half_rn(Wq[base + e]);
        return;
    }
    if (bid >= 3712) {                   // P6: Wfc fp16 transpose
        int i = bid - 3712;
        int n0 = (i % 1064) * 32, k0 = (i / 1064) * 32;
        for (int j = ty; j < 32; j += 8) {
            int n = n0 + tx;
            tile[j][tx] = (n < VOCAB) ? Wfc[(size_t)(k0 + j) * VOCAB + n] : 0.f;
        }
        __syncthreads();
        for (int j = ty; j < 32; j += 8)
            wT_h[(size_t)(n0 + j) * UNITS + k0 + tx] = __float2half_rn(tile[tx][j]);
        return;
    }

    const float* W; int K, N, ldn, Kpad, mode, n0, k0;
    __nv_bfloat16 *hi, *lo;
    if (bid < 256) {
        int i = bid; W = Wm; K = 512; N = 512; ldn = 512; Kpad = 512; mode = 0;
        hi = wmT_h; lo = wmT_l; n0 = (i % 16) * 32; k0 = (i / 16) * 32;
    } else if (bid < 896) {
        int i = bid - 256; W = Wk; K = EMB; N = 2048; ldn = 2048; Kpad = EMBP; mode = 0;
        hi = wk0T_h; lo = wk0T_l; n0 = (i % 64) * 32; k0 = (i / 64) * 32;
    } else if (bid < 1920) {
        int i = bid - 896; W = Wk + (size_t)EMB * 2048; K = 512; N = 2048;
        ldn = 2048; Kpad = 512; mode = 0;
        hi = wkpT_h; lo = wkpT_l; n0 = (i % 64) * 32; k0 = (i / 64) * 32;
    } else if (bid < 3200) {
        int i = bid - 2176; W = Uk; K = 512; N = 2048; ldn = 2048; Kpad = 512; mode = 2;
        hi = uk0H; lo = uk0L; n0 = (i % 64) * 32; k0 = (i / 64) * 32;
    } else {
        int i = bid - 3200; W = Wa; K = 1024; N = 512; ldn = 512; Kpad = 1024; mode = 0;
        hi = waT_h; lo = waT_l; n0 = (i % 16) * 32; k0 = (i / 16) * 32;
    }

    for (int j = ty; j < 32; j += 8) {
        int k = k0 + j, n = n0 + tx;
        tile[j][tx] = (k < K && n < N) ? W[(size_t)k * ldn + n] : 0.f;
    }
    __syncthreads();
    for (int j = ty; j < 32; j += 8) {
        int n = n0 + j, k = k0 + tx;
        float v = tile[tx][j];
        int nn = (mode == 2) ? ((n & 511) * 4 + (n >> 9)) : n;
        __nv_bfloat16 h = __float2bfloat16(v);
        hi[(size_t)nn * Kpad + k] = h;
        lo[(size_t)nn * Kpad + k] = __float2bfloat16(v - __bfloat162float(h));
    }
}

// ---------------------------------------------------------------------------
// Core split-bf16 3-term mma GEMM (fp32 A on the fly, pre-split B).
#define FTS     72
#define F_ARR   (128 * FTS * 2)
#define F_STAGE (4 * F_ARR)
#define F_SMEM  (2 * F_STAGE)

template<int MODE>
__device__ __forceinline__ void gemm_core(
    char* dsm, int m0, int n0,
    const float* __restrict__ A, int lda, int M, int N, int K,
    const __nv_bfloat16* __restrict__ BhT,
    const __nv_bfloat16* __restrict__ BlT,
    const float* __restrict__ bias,
    float* __restrict__ C, int ldc,
    __half* __restrict__ Ch,
    __nv_bfloat16* __restrict__ OH, __nv_bfloat16* __restrict__ OL)
{
    const int tid  = threadIdx.x;
    const int wid  = tid >> 5, lane = tid & 31;
    const int wm   = wid & 1,  wn   = wid >> 1;
    const int mbase = wm * 64, nbase = wn * 32;
    const uint32_t sb = smem_u32(dsm);
    const int NIT = K >> 6;

    float acc[16][4];
#pragma unroll
    for (int i = 0; i < 16; i++)
#pragma unroll
        for (int j = 0; j < 4; j++) acc[i][j] = 0.f;

    float4 Areg[8];
    auto loadA = [&](int it) {
        int koff = it * 64;
#pragma unroll
        for (int l = 0; l < 8; l++) {
            int q = tid + l * 256;
            int r = q >> 4, c4 = (q & 15) * 4;
            int gm = m0 + r;
            Areg[l] = (gm < M) ? *(const float4*)(A + (size_t)gm * lda + koff + c4)
                               : make_float4(0.f, 0.f, 0.f, 0.f);
        }
    };
    auto storeA = [&](int stage) {
#pragma unroll
        for (int l = 0; l < 8; l++) {
            int q = tid + l * 256;
            int r = q >> 4, c4 = (q & 15) * 4;
            float4 v = Areg[l];
            uint32_t off = (uint32_t)(r * FTS + c4) * 2;
            uint2 hi = make_uint2(pack_bf2(v.x, v.y), pack_bf2(v.z, v.w));
            uint2 lo = make_uint2(pack_bf2(bf_res(v.x), bf_res(v.y)),
                                  pack_bf2(bf_res(v.z), bf_res(v.w)));
            *(uint2*)(dsm + stage * F_STAGE + 0 * F_ARR + off) = hi;
            *(uint2*)(dsm + stage * F_STAGE + 1 * F_ARR + off) = lo;
        }
    };
    auto issueB = [&](int it, int stage) {
        int koff = it * 64;
#pragma unroll
        for (int arr = 0; arr < 2; arr++) {
            const __nv_bfloat16* src = arr ? BlT : BhT;
#pragma unroll
            for (int l = 0; l < 4; l++) {
                int q = tid + l * 256;
                int r = q >> 3, c8 = (q & 7) * 8;
                uint32_t dst = sb + stage * F_STAGE + (2 + arr) * F_ARR
                             + (uint32_t)(r * FTS + c8) * 2;
                cp_async16(dst, src + (size_t)(n0 + r) * K + koff + c8);
            }
        }
        cp_commit();
    };
    auto compute = [&](int stage) {
        uint32_t aHb = sb + stage * F_STAGE;
        uint32_t aLb = aHb + F_ARR;
        uint32_t bHb = aHb + 2 * F_ARR;
        uint32_t bLb = aHb + 3 * F_ARR;
#pragma unroll
        for (int ks = 0; ks < 4; ks++) {
            uint32_t a_off = (uint32_t)(((mbase + (lane & 15)) * FTS
                              + ks * 16 + (lane >> 4) * 8) * 2);
            uint32_t aH[4][4], aL[4][4];
#pragma unroll
            for (int i = 0; i < 4; i++) {
                uint32_t o = a_off + (uint32_t)(i * 16 * FTS * 2);
                ldm_x4(aH[i][0], aH[i][1], aH[i][2], aH[i][3], aHb + o);
                ldm_x4(aL[i][0], aL[i][1], aL[i][2], aL[i][3], aLb + o);
            }
            uint32_t b_off = (uint32_t)(((nbase + (lane & 7) + (lane >> 4) * 8) * FTS
                              + ks * 16 + ((lane >> 3) & 1) * 8) * 2);
            uint32_t bH[4][2], bL[4][2];
#pragma unroll
            for (int jp = 0; jp < 2; jp++) {
                uint32_t o = b_off + (uint32_t)(jp * 16 * FTS * 2);
                ldm_x4(bH[jp*2][0], bH[jp*2][1], bH[jp*2+1][0], bH[jp*2+1][1], bHb + o);
                ldm_x4(bL[jp*2][0], bL[jp*2][1], bL[jp*2+1][0], bL[jp*2+1][1], bLb + o);
            }
#pragma unroll
            for (int i = 0; i < 4; i++)
#pragma unroll
                for (int j = 0; j < 4; j++) {
                    mma_bf16(acc[i * 4 + j], aH[i], bH[j]);
                    mma_bf16(acc[i * 4 + j], aH[i], bL[j]);
                    mma_bf16(acc[i * 4 + j], aL[i], bH[j]);
                }
        }
    };

    loadA(0);
    issueB(0, 0);
    if (NIT > 1) issueB(1, 1);
    for (int it = 0; it < NIT; it++) {
        int stage = it & 1;
        if (it >= NIT - 2) cp_wait<0>(); else cp_wait<1>();
        storeA(stage);
        __syncthreads();
        if (it + 1 < NIT) loadA(it + 1);
        compute(stage);
        __syncthreads();
        if (it + 2 < NIT) issueB(it + 2, stage);
    }

#pragma unroll
    for (int i = 0; i < 4; i++) {
        int row0 = m0 + mbase + i * 16 + (lane >> 2);
#pragma unroll
        for (int j = 0; j < 4; j++) {
            int col = n0 + nbase + j * 8 + (lane & 3) * 2;
            if (col >= N) continue;
            const float* c = acc[i * 4 + j];
#pragma unroll
            for (int hrow = 0; hrow < 2; hrow++) {
                int gm = row0 + hrow * 8;
                if (gm >= M) continue;
                float v0 = c[hrow * 2 + 0], v1 = c[hrow * 2 + 1];
                if (MODE == 0) {
                    float b0 = bias ? bias[col] : 0.f;
                    float b1 = bias ? bias[col + 1] : 0.f;
                    C[(size_t)gm * ldc + col]     = v0 + b0;
                    C[(size_t)gm * ldc + col + 1] = v1 + b1;
                } else if (MODE == 1) {
                    Ch[(size_t)gm * ldc + col]     = __float2half_rn(v0);
                    Ch[(size_t)gm * ldc + col + 1] = __float2half_rn(v1);
                } else {   // MODE 3
                    if (gm < 512) {
                        v0 += bias[(size_t)gm * 2048 + col];
                        v1 += bias[(size_t)gm * 2048 + col + 1];
                    }
                    int np0 = (col & 511) * 4 + (col >> 9);
                    int np1 = ((col + 1) & 511) * 4 + ((col + 1) >> 9);
                    __nv_bfloat16 h0 = __float2bfloat16(v0);
                    __nv_bfloat16 h1 = __float2bfloat16(v1);
                    OH[(size_t)np0 * 1024 + gm] = h0;
                    OL[(size_t)np0 * 1024 + gm] =
                        __float2bfloat16(v0 - __bfloat162float(h0));
                    OH[(size_t)np1 * 1024 + gm] = h1;
                    OL[(size_t)np1 * 1024 + gm] =
                        __float2bfloat16(v1 - __bfloat162float(h1));
                }
            }
        }
    }
}

// gemm3: keys->fp16 (120) + zpre (256) + wbig (128) in one launch.
__global__ void __launch_bounds__(256)
gemm3_kernel(const float* __restrict__ mem,
             const __nv_bfloat16* __restrict__ wmT_h,
             const __nv_bfloat16* __restrict__ wmT_l,
             __half* __restrict__ keysh,
             const float* __restrict__ embA,
             const __nv_bfloat16* __restrict__ wk0T_h,
             const __nv_bfloat16* __restrict__ wk0T_l,
             const float* __restrict__ bk,
             float* __restrict__ zpre,
             const float* __restrict__ Wa,
             const __nv_bfloat16* __restrict__ wkpT_h,
             const __nv_bfloat16* __restrict__ wkpT_l,
             const float* __restrict__ Uk,
             __nv_bfloat16* __restrict__ wkuH,
             __nv_bfloat16* __restrict__ wkuL)
{
    extern __shared__ char dsm[];
    int bid = blockIdx.x;
    if (bid < 120) {
        int m0 = (bid % 30) * 128, n0 = (bid / 30) * 128;
        gemm_core<1>(dsm, m0, n0, mem, UNITS, B64 * TIN, UNITS, UNITS,
                     wmT_h, wmT_l, nullptr, nullptr, UNITS, keysh,
                     nullptr, nullptr);
    } else if (bid < 376) {
        int p = bid - 120;
        int m0 = (p % 16) * 128, n0 = (p / 16) * 128;
        gemm_core<0>(dsm, m0, n0, embA, EMBP, ROWS, 2048, EMBP,
                     wk0T_h, wk0T_l, bk, zpre, 2048, nullptr,
                     nullptr, nullptr);
    } else {
        int p = bid - 376;
        int m0 = (p % 8) * 128, n0 = (p / 8) * 128;
        gemm_core<3>(dsm, m0, n0, Wa, UNITS, 1024, 2048, UNITS,
                     wkpT_h, wkpT_l, Uk, nullptr, 0, nullptr,
                     wkuH, wkuL);
    }
}

__global__ void __launch_bounds__(256)
gemm_states_kernel(const float* __restrict__ hctx,
                   const __nv_bfloat16* __restrict__ waT_h,
                   const __nv_bfloat16* __restrict__ waT_l,
                   __half* __restrict__ sA_h)
{
    extern __shared__ char dsm[];
    int m0 = blockIdx.x * 128, n0 = blockIdx.y * 128;
    gemm_core<1>(dsm, m0, n0, hctx, 1024, ROWS, UNITS, 1024,
                 waT_h, waT_l, nullptr, nullptr, UNITS, sA_h,
                 nullptr, nullptr);
}

// ---------------------------------------------------------------------------
// PERSISTENT step loop: 128 CTAs x 512 threads (R11 structure).
// Gates: tile 64m x 16n', BK=64, 3-stage. Attention: CTAs 0..63, q-GEMV
// vectorized (uint4, 8 k-slices, smem reduction).
#define PTS     72
#define P_AH    0
#define P_AL    9216
#define P_BH    18432
#define P_BL    20736
#define P_STAGE 23040
#define P_SMEM  (3 * P_STAGE)    // 69120 B

__global__ void __launch_bounds__(512, 1)
step_loop_kernel(const float* __restrict__ h0,
                 const float* __restrict__ c0,
                 const __nv_bfloat16* __restrict__ uk0H,
                 const __nv_bfloat16* __restrict__ uk0L,
                 const __nv_bfloat16* __restrict__ wkuH,
                 const __nv_bfloat16* __restrict__ wkuL,
                 const float* __restrict__ zpre,
                 float* __restrict__ cbuf,
                 float* __restrict__ hctx,
                 const __half* __restrict__ wqKh,   // [k][n]
                 const __half* __restrict__ keysh,
                 const float* __restrict__ memory,
                 const float* __restrict__ v_att)
{
    extern __shared__ char dsm[];
    const int cta  = blockIdx.x;              // 0..127
    const int tid  = threadIdx.x;
    const int wid  = tid >> 5, lane = tid & 31;
    const int mbase = (wid & 3) * 16;
    const int nbase = (wid >> 2) * 8;
    const int n0   = cta * 16;
    const uint32_t sb = smem_u32(dsm);
    const int nCTA = gridDim.x;

    for (int t = 0; t < TOUT; t++) {
        // ================= gates phase =================
        const float* Aptr; int astride, K;
        const __nv_bfloat16 *BH, *BL;
        if (t == 0) { Aptr = h0; astride = UNITS; K = 512; BH = uk0H; BL = uk0L; }
        else { Aptr = hctx + (size_t)(t - 1) * 1024; astride = HLD; K = 1024;
               BH = wkuH; BL = wkuL; }
        const float* cprev = t ? (cbuf + (size_t)((t - 1) & 1) * B64 * UNITS) : c0;
        float* cnew = cbuf + (size_t)(t & 1) * B64 * UNITS;
        const int NIT = K >> 6;

        float acc[4] = {0.f, 0.f, 0.f, 0.f};
        float4 Areg[2];

        auto issueB = [&](int it, int stage) {
            int koff = it * 64;
            if (tid < 256) {
                int arr = tid >> 7;
                int rem = tid & 127;
                int r   = rem >> 3;
                int c8  = (rem & 7) * 8;
                const __nv_bfloat16* src = arr ? BL : BH;
                uint32_t dst = sb + stage * P_STAGE + (arr ? P_BL : P_BH)
                             + (uint32_t)(r * PTS + c8) * 2;
                cp_async16(dst, src + (size_t)(n0 + r) * K + koff + c8);
            }
            cp_commit();
        };
        auto loadA = [&](int it) {
            int koff = it * 64;
#pragma unroll
            for (int l = 0; l < 2; l++) {
                int q = tid + l * 512;
                int r = q >> 4, c4 = (q & 15) * 4;
                Areg[l] = *(const float4*)(Aptr + (size_t)r * astride + koff + c4);
            }
        };
        auto storeA = [&](int stage) {
#pragma unroll
            for (int l = 0; l < 2; l++) {
                int q = tid + l * 512;
                int r = q >> 4, c4 = (q & 15) * 4;
                float4 v = Areg[l];
                uint32_t off = (uint32_t)(r * PTS + c4) * 2;
                uint2 hi = make_uint2(pack_bf2(v.x, v.y), pack_bf2(v.z, v.w));
                uint2 lo = make_uint2(pack_bf2(bf_res(v.x), bf_res(v.y)),
                                      pack_bf2(bf_res(v.z), bf_res(v.w)));
                *(uint2*)(dsm + stage * P_STAGE + P_AH + off) = hi;
                *(uint2*)(dsm + stage * P_STAGE + P_AL + off) = lo;
            }
        };
        auto compute = [&](int stage) {
            uint32_t aHb = sb + stage * P_STAGE + P_AH;
            uint32_t aLb = sb + stage * P_STAGE + P_AL;
            uint32_t bHb = sb + stage * P_STAGE + P_BH;
            uint32_t bLb = sb + stage * P_STAGE + P_BL;
#pragma unroll
            for (int ks = 0; ks < 4; ks++) {
                uint32_t a_off = (uint32_t)(((mbase + (lane & 15)) * PTS
                                  + ks * 16 + (lane >> 4) * 8) * 2);
                uint32_t aH[4], aL[4];
                ldm_x4(aH[0], aH[1], aH[2], aH[3], aHb + a_off);
                ldm_x4(aL[0], aL[1], aL[2], aL[3], aLb + a_off);
                uint32_t b_off = (uint32_t)(((nbase + (lane & 7)) * PTS
                                  + ks * 16 + ((lane >> 3) & 1) * 8) * 2);
                uint32_t bH[2], bL[2];
                ldm_x2(bH[0], bH[1], bHb + b_off);
                ldm_x2(bL[0], bL[1], bLb + b_off);
                mma_bf16(acc, aH, bH);
                mma_bf16(acc, aH, bL);
                mma_bf16(acc, aL, bH);
            }
        };

        loadA(0);
        issueB(0, 0);
        issueB(1, 1);
        issueB(2, 2);
        for (int it = 0; it < NIT; it++) {
            int stage = it % 3;
            if (it + 3 <= NIT)      cp_wait<2>();
            else if (it + 2 == NIT) cp_wait<1>();
            else                    cp_wait<0>();
            storeA(stage);
            __syncthreads();
            if (it + 1 < NIT) loadA(it + 1);
            if (wid < 8) compute(stage);
            __syncthreads();
            if (it + 3 < NIT) issueB(it + 3, stage);
        }

        // ---- LSTM epilogue ----
        float* zbuf = (float*)dsm;               // [64][20]
        if (wid < 8) {
            int row = mbase + (lane >> 2);
            int col = nbase + (lane & 3) * 2;
            zbuf[row * 20 + col]           = acc[0];
            zbuf[row * 20 + col + 1]       = acc[1];
            zbuf[(row + 8) * 20 + col]     = acc[2];
            zbuf[(row + 8) * 20 + col + 1] = acc[3];
        }
        __syncthreads();
        if (tid < 256) {
            int b  = tid >> 2, ul = tid & 3;
            int u  = cta * 4 + ul;
            const float* ad = zpre + (size_t)t * B64 * 2048 + (size_t)b * 2048;
            float zi = zbuf[b * 20 + ul * 4 + 0] + ad[u];
            float zf = zbuf[b * 20 + ul * 4 + 1] + ad[512 + u];
            float zg = zbuf[b * 20 + ul * 4 + 2] + ad[1024 + u];
            float zo = zbuf[b * 20 + ul * 4 + 3] + ad[1536 + u];
            float si = fast_sigmoid(zi);
            float sf = fast_sigmoid(zf);
            float so = fast_sigmoid(zo);
            float tg = fast_tanh(zg);
            float c  = sf * cprev[(size_t)b * UNITS + u] + si * tg;
            float h  = so * fast_tanh(c);
            cnew[(size_t)b * UNITS + u] = c;
            hctx[(size_t)b * HLD + (size_t)t * 1024 + u] = h;
        }

        grid_barrier(nCTA);

        // ================= attention phase (CTAs 0..63) =================
        if (cta < B64) {
            int b = cta;
            float* sh    = (float*)dsm;            // 512
            float* sq    = sh + 512;               // 512
            float* ssc   = sq + 512;               // 64
            float* qpart = ssc + 64;               // 8 x 512 = 4096
            float* hrow = hctx + (size_t)b * HLD + (size_t)t * 1024;

            sh[tid] = hrow[tid];
            __syncthreads();
            {   // q-GEMV vectorized: thread = (kslice = tid>>6, 8 n-cols)
                int kslice = tid >> 6;             // 0..7 (64 k each)
                int n8 = (tid & 63) * 8;           // n base
                float a[8];
#pragma unroll
                for (int j = 0; j < 8; j++) a[j] = 0.f;
                const __half* wp = wqKh + (size_t)(kslice * 64) * UNITS + n8;
                const float* shk = sh + kslice * 64;
#pragma unroll 4
                for (int k = 0; k < 64; k++) {
                    float hk = shk[k];
                    uint4 raw = *(const uint4*)(wp + (size_t)k * UNITS);
                    float2 f0 = __half22float2(*(__half2*)&raw.x);
                    float2 f1 = __half22float2(*(__half2*)&raw.y);
                    float2 f2 = __half22float2(*(__half2*)&raw.z);
                    float2 f3 = __half22float2(*(__half2*)&raw.w);
                    a[0] = fmaf(hk, f0.x, a[0]);
                    a[1] = fmaf(hk, f0.y, a[1]);
                    a[2] = fmaf(hk, f1.x, a[2]);
                    a[3] = fmaf(hk, f1.y, a[3]);
                    a[4] = fmaf(hk, f2.x, a[4]);
                    a[5] = fmaf(hk, f2.y, a[5]);
                    a[6] = fmaf(hk, f3.x, a[6]);
                    a[7] = fmaf(hk, f3.y, a[7]);
                }
                float* qp = qpart + kslice * 512 + n8;
#pragma unroll
                for (int j = 0; j < 8; j++) qp[j] = a[j];
            }
            __syncthreads();
            {   // reduce 8 k-slices
                float s = 0.f;
#pragma unroll
                for (int sl = 0; sl < 8; sl++) s += qpart[sl * 512 + tid];
                sq[tid] = s;
            }
            __syncthreads();

            for (int s = wid; s < TIN; s += 16) {
                const __half* krow = keysh + ((size_t)b * TIN + s) * UNITS;
                float sc = 0.f;
#pragma unroll 4
                for (int u = lane; u < UNITS; u += 32)
                    sc += fast_tanh(__half2float(krow[u]) + sq[u]) * v_att[u];
#pragma unroll
                for (int off = 16; off; off >>= 1)
                    sc += __shfl_xor_sync(~0u, sc, off);
                if (lane == 0) ssc[s] = sc;
            }
            __syncthreads();

            if (tid < 32) {
                float m = -1e30f;
                for (int s = lane; s < TIN; s += 32) m = fmaxf(m, ssc[s]);
#pragma unroll
                for (int off = 16; off; off >>= 1)
                    m = fmaxf(m, __shfl_xor_sync(~0u, m, off));
                float ssum = 0.f;
                for (int s = lane; s < TIN; s += 32) {
                    float e = __expf(ssc[s] - m);
                    ssc[s] = e; ssum += e;
                }
#pragma unroll
                for (int off = 16; off; off >>= 1)
                    ssum += __shfl_xor_sync(~0u, ssum, off);
                float inv = __fdividef(1.f, ssum);
                for (int s = lane; s < TIN; s += 32) ssc[s] *= inv;
            }
            __syncthreads();

            const float* mrow = memory + (size_t)b * TIN * UNITS;
            float accc = 0.f;
#pragma unroll 4
            for (int s = 0; s < TIN; s++)
                accc = fmaf(ssc[s], mrow[(size_t)s * UNITS + tid], accc);
            hrow[512 + tid] = accc;
        }

        grid_barrier(nCTA);
    }
}

// ---------------------------------------------------------------------------
// Vocab GEMM: 1-term fp16.
#define V_ARR   (128 * FTS * 2)
#define V_STAGE (2 * V_ARR)
#define V_SMEM  (2 * V_STAGE)

__global__ void __launch_bounds__(256)
gemm_vocab_f16(const __half* __restrict__ Ah,
               const __half* __restrict__ Bh,
               const float* __restrict__ bias,
               float* __restrict__ out)
{
    extern __shared__ char dsm[];
    const int m0 = blockIdx.x * 128;
    const int n0 = blockIdx.y * 128;
    const int tid  = threadIdx.x;
    const int wid  = tid >> 5, lane = tid & 31;
    const int wm   = wid & 1,  wn   = wid >> 1;
    const int mbase = wm * 64, nbase = wn * 32;
    const uint32_t sb = smem_u32(dsm);

    float acc[16][4];
#pragma unroll
    for (int i = 0; i < 16; i++)
#pragma unroll
        for (int j = 0; j < 4; j++) acc[i][j] = 0.f;

    auto issue = [&](int it, int stage) {
        int koff = it * 64;
#pragma unroll
        for (int arr = 0; arr < 2; arr++) {
            const __half* src = arr ? Bh : Ah;
            const int rbase = arr ? n0 : m0;
#pragma unroll
            for (int l = 0; l < 4; l++) {
                int q = tid + l * 256;
                int r = q >> 3, c8 = (q & 7) * 8;
                uint32_t dst = sb + stage * V_STAGE + arr * V_ARR
                             + (uint32_t)(r * FTS + c8) * 2;
                cp_async16(dst, src + (size_t)(rbase + r) * UNITS + koff + c8);
            }
        }
        cp_commit();
    };
    auto compute = [&](int stage) {
        uint32_t aHb = sb + stage * V_STAGE;
        uint32_t bHb = aHb + V_ARR;
#pragma unroll
        for (int ks = 0; ks < 4; ks++) {
            uint32_t a_off = (uint32_t)(((mbase + (lane & 15)) * FTS
                              + ks * 16 + (lane >> 4) * 8) * 2);
            uint32_t aH[4][4];
#pragma unroll
            for (int i = 0; i < 4; i++) {
                uint32_t o = a_off + (uint32_t)(i * 16 * FTS * 2);
                ldm_x4(aH[i][0], aH[i][1], aH[i][2], aH[i][3], aHb + o);
            }
            uint32_t b_off = (uint32_t)(((nbase + (lane & 7) + (lane >> 4) * 8) * FTS
                              + ks * 16 + ((lane >> 3) & 1) * 8) * 2);
            uint32_t bH[4][2];
#pragma unroll
            for (int jp = 0; jp < 2; jp++) {
                uint32_t o = b_off + (uint32_t)(jp * 16 * FTS * 2);
                ldm_x4(bH[jp*2][0], bH[jp*2][1], bH[jp*2+1][0], bH[jp*2+1][1], bHb + o);
            }
#pragma unroll
            for (int i = 0; i < 4; i++)
#pragma unroll
                for (int j = 0; j < 4; j++)
                    mma_f16(acc[i * 4 + j], aH[i], bH[j]);
        }
    };

    issue(0, 0);
    issue(1, 1);
    for (int it = 0; it < 8; it++) {
        int stage = it & 1;
        if (it >= 6) cp_wait<0>(); else cp_wait<1>();
        __syncthreads();
        compute(stage);
        __syncthreads();
        if (it + 2 < 8) issue(it + 2, stage);
    }

#pragma unroll
    for (int i = 0; i < 4; i++) {
        int row0 = m0 + mbase + i * 16 + (lane >> 2);
#pragma unroll
        for (int j = 0; j < 4; j++) {
            int col = n0 + nbase + j * 8 + (lane & 3) * 2;
            if (col >= VOCAB) continue;
            float b0 = bias[col], b1 = bias[col + 1];
            const float* c = acc[i * 4 + j];
            if (row0 < ROWS) {
                out[(size_t)row0 * VOCAB + col]     = c[0] + b0;
                out[(size_t)row0 * VOCAB + col + 1] = c[1] + b1;
            }
            if (row0 + 8 < ROWS) {
                out[(size_t)(row0 + 8) * VOCAB + col]     = c[2] + b0;
                out[(size_t)(row0 + 8) * VOCAB + col + 1] = c[3] + b1;
            }
        }
    }
}

// ---------------------------------------------------------------------------
static inline float* sym_addr(const void* sym) {
    void* p = nullptr;
    cudaGetSymbolAddress(&p, sym);
    return (float*)p;
}
static inline __nv_bfloat16* sym_addr_bf(const void* sym) {
    void* p = nullptr;
    cudaGetSymbolAddress(&p, sym);
    return (__nv_bfloat16*)p;
}
static inline __half* sym_addr_h(const void* sym) {
    void* p = nullptr;
    cudaGetSymbolAddress(&p, sym);
    return (__half*)p;
}

extern "C" void kernel_launch(void* const* d_in, const int* in_sizes, int n_in,
                              void* d_out, int out_size)
{
    const int*   dec = (const int*)  d_in[0];
    const float* h0  = (const float*)d_in[1];
    const float* c0  = (const float*)d_in[2];
    const float* mem = (const float*)d_in[3];
    const float* emb = (const float*)d_in[4];
    const float* Wk  = (const float*)d_in[5];
    const float* Uk  = (const float*)d_in[6];
    const float* bk  = (const float*)d_in[7];
    const float* Wm  = (const float*)d_in[8];
    const float* Wq  = (const float*)d_in[9];
    const float* vat = (const float*)d_in[10];
    const float* Wa  = (const float*)d_in[11];
    const float* Wfc = (const float*)d_in[12];
    const float* bfc = (const float*)d_in[13];
    float* out = (float*)d_out;

    float* embA   = sym_addr(g_embA);
    float* zpre   = sym_addr(g_zpre);
    float* cbuf   = sym_addr(g_cbuf);
    float* hctx   = sym_addr(g_hctx);
    __half* keysh = sym_addr_h(g_keysh);
    __half* wqKh  = sym_addr_h(g_wqKh);
    __half* sA_h  = sym_addr_h(g_sA_h);
    __half* wT_h  = sym_addr_h(g_wT_h);
    __nv_bfloat16* wkuH = sym_addr_bf(g_wkuH);
    __nv_bfloat16* wkuL = sym_addr_bf(g_wkuL);
    __nv_bfloat16* uk0H = sym_addr_bf(g_uk0H);
    __nv_bfloat16* uk0L = sym_addr_bf(g_uk0L);
    __nv_bfloat16* wmT_h  = sym_addr_bf(g_wmT_h);
    __nv_bfloat16* wmT_l  = sym_addr_bf(g_wmT_l);
    __nv_bfloat16* wk0T_h = sym_addr_bf(g_wk0T_h);
    __nv_bfloat16* wk0T_l = sym_addr_bf(g_wk0T_l);
    __nv_bfloat16* wkpT_h = sym_addr_bf(g_wkpT_h);
    __nv_bfloat16* wkpT_l = sym_addr_bf(g_wkpT_l);
    __nv_bfloat16* waT_h  = sym_addr_bf(g_waT_h);
    __nv_bfloat16* waT_l  = sym_addr_bf(g_waT_l);

    cudaFuncSetAttribute(gemm3_kernel,
                         cudaFuncAttributeMaxDynamicSharedMemorySize, F_SMEM);
    cudaFuncSetAttribute(gemm_states_kernel,
                         cudaFuncAttributeMaxDynamicSharedMemorySize, F_SMEM);
    cudaFuncSetAttribute(step_loop_kernel,
                         cudaFuncAttributeMaxDynamicSharedMemorySize, P_SMEM);
    cudaFuncSetAttribute(gemm_vocab_f16,
                         cudaFuncAttributeMaxDynamicSharedMemorySize, V_SMEM);

    // 1: gather
    gather_emb_kernel<<<ROWS, 128>>>(dec, emb, embA);
    // 2: all weight converts
    mega_convert_kernel<<<20736, 256>>>(Wm, Wk, Uk, Wq, Wa, Wfc,
                                        wmT_h, wmT_l, wk0T_h, wk0T_l,
                                        wkpT_h, wkpT_l, wqKh, uk0H, uk0L,
                                        waT_h, waT_l, wT_h);
    // 3: keys(fp16) + zpre + wbig
    gemm3_kernel<<<504, 256, F_SMEM>>>(mem, wmT_h, wmT_l, keysh,
                                       embA, wk0T_h, wk0T_l, bk, zpre,
                                       Wa, wkpT_h, wkpT_l, Uk, wkuH, wkuL);
    // 4: persistent step loop (128 CTAs)  <-- ncu capture target
    step_loop_kernel<<<128, 512, P_SMEM>>>(
        h0, c0, uk0H, uk0L, wkuH, wkuL, zpre, cbuf, hctx,
        wqKh, keysh, mem, vat);
    // 5: states = hctx @ Wa -> fp16
    gemm_states_kernel<<<dim3(16, 4), 256, F_SMEM>>>(hctx, waT_h, waT_l, sA_h);
    // 6: vocab projection
    gemm_vocab_f16<<<dim3(MPAD / 128, VPAD / 128), 256, V_SMEM>>>(
        sA_h, wT_h, bfc, out);
}

// round 16
// speedup vs baseline: 1.2135x; 1.0651x over previous
#include <cuda_runtime.h>
#include <cuda.h>
#include <cuda_bf16.h>
#include <cuda_fp16.h>
#include <math.h>
#include <stdint.h>

// ============================================================================
// Attention-LSTM decoder. B=64, T_out=31, T_in=60, U=512, EMB=300, VOCAB=34004.
// R13 base (proven 1425us) + gates 3-term accumulators + ctx 4 partials.
// (Wfc convert kept in pre-loop mega_convert: R14's hidden-convert variant is
//  suspected in two container failures; de-risked here.)
//   1 gather_emb   2 mega_convert (incl Wfc)  3 gemm3
//   4 step_loop (128 CTAs)   5 states GEMM   6 vocab GEMM
// ============================================================================

#define B64   64
#define TOUT  31
#define TIN   60
#define UNITS 512
#define EMB   300
#define EMBP  320
#define VOCAB 34004
#define ROWS  (B64 * TOUT)     // 1984
#define MPAD  2048
#define VPAD  34048            // 266 * 128
#define HLD   (TOUT * 1024)

// ---------------- scratch ----------------------------------------------------
__device__ float g_embA  [ROWS * EMBP];
__device__ float g_zpre  [ROWS * 4 * UNITS];
__device__ float g_cbuf  [2][B64 * UNITS];
__device__ float g_hctx  [ROWS * 1024];
__device__ __align__(16) __half g_keysh[B64 * TIN * UNITS];      // fp16 keys
__device__ __align__(16) __half g_wqKh [UNITS * UNITS];          // Wq [k][n] fp16
__device__ __align__(16) __half g_sA_h[MPAD * UNITS];            // pad rows stay 0
__device__ __align__(16) __half g_wT_h [(size_t)VPAD * UNITS];   // fp16 [n][k]
__device__ __align__(16) __nv_bfloat16 g_wkuH[2048 * 1024];      // [n'][k]
__device__ __align__(16) __nv_bfloat16 g_wkuL[2048 * 1024];
__device__ __align__(16) __nv_bfloat16 g_uk0H[2048 * 512];
__device__ __align__(16) __nv_bfloat16 g_uk0L[2048 * 512];
__device__ __align__(16) __nv_bfloat16 g_wmT_h [512 * 512];
__device__ __align__(16) __nv_bfloat16 g_wmT_l [512 * 512];
__device__ __align__(16) __nv_bfloat16 g_wk0T_h[2048 * EMBP];
__device__ __align__(16) __nv_bfloat16 g_wk0T_l[2048 * EMBP];
__device__ __align__(16) __nv_bfloat16 g_wkpT_h[2048 * 512];
__device__ __align__(16) __nv_bfloat16 g_wkpT_l[2048 * 512];
__device__ __align__(16) __nv_bfloat16 g_waT_h [512 * 1024];
__device__ __align__(16) __nv_bfloat16 g_waT_l [512 * 1024];

__device__ int g_bar_cnt = 0;
__device__ volatile unsigned g_bar_gen = 0;

// ---------------- PTX helpers -------------------------------------------------
__device__ __forceinline__ uint32_t smem_u32(const void* p) {
    uint32_t a;
    asm("{ .reg .u64 t; cvta.to.shared.u64 t, %1; cvt.u32.u64 %0, t; }" : "=r"(a) : "l"(p));
    return a;
}
__device__ __forceinline__ void ldm_x4(uint32_t& r0, uint32_t& r1, uint32_t& r2,
                                       uint32_t& r3, uint32_t addr) {
    asm volatile("ldmatrix.sync.aligned.m8n8.x4.shared.b16 {%0,%1,%2,%3}, [%4];"
                 : "=r"(r0), "=r"(r1), "=r"(r2), "=r"(r3) : "r"(addr));
}
__device__ __forceinline__ void ldm_x2(uint32_t& r0, uint32_t& r1, uint32_t addr) {
    asm volatile("ldmatrix.sync.aligned.m8n8.x2.shared.b16 {%0,%1}, [%2];"
                 : "=r"(r0), "=r"(r1) : "r"(addr));
}
__device__ __forceinline__ void mma_bf16(float* c, const uint32_t* a, const uint32_t* b) {
    asm volatile("mma.sync.aligned.m16n8k16.row.col.f32.bf16.bf16.f32 "
                 "{%0,%1,%2,%3}, {%4,%5,%6,%7}, {%8,%9}, {%0,%1,%2,%3};"
                 : "+f"(c[0]), "+f"(c[1]), "+f"(c[2]), "+f"(c[3])
                 : "r"(a[0]), "r"(a[1]), "r"(a[2]), "r"(a[3]), "r"(b[0]), "r"(b[1]));
}
__device__ __forceinline__ void mma_f16(float* c, const uint32_t* a, const uint32_t* b) {
    asm volatile("mma.sync.aligned.m16n8k16.row.col.f32.f16.f16.f32 "
                 "{%0,%1,%2,%3}, {%4,%5,%6,%7}, {%8,%9}, {%0,%1,%2,%3};"
                 : "+f"(c[0]), "+f"(c[1]), "+f"(c[2]), "+f"(c[3])
                 : "r"(a[0]), "r"(a[1]), "r"(a[2]), "r"(a[3]), "r"(b[0]), "r"(b[1]));
}
__device__ __forceinline__ void cp_async16(uint32_t dst, const void* src) {
    asm volatile("cp.async.cg.shared.global [%0], [%1], 16;" :: "r"(dst), "l"(src));
}
__device__ __forceinline__ void cp_commit() { asm volatile("cp.async.commit_group;"); }
template<int N> __device__ __forceinline__ void cp_wait() {
    asm volatile("cp.async.wait_group %0;" :: "n"(N));
}
__device__ __forceinline__ uint32_t pack_bf2(float a, float b) {
    __nv_bfloat162 t = __floats2bfloat162_rn(a, b);
    return *reinterpret_cast<uint32_t*>(&t);
}
__device__ __forceinline__ float bf_res(float a) {
    return a - __bfloat162float(__float2bfloat16(a));
}
__device__ __forceinline__ float fast_tanh(float x) {
    float e = __expf(2.f * x);
    return 1.f - __fdividef(2.f, e + 1.f);
}
__device__ __forceinline__ float fast_sigmoid(float x) {
    return __fdividef(1.f, 1.f + __expf(-x));
}
__device__ __forceinline__ void grid_barrier(int nCTA) {
    __syncthreads();
    if (threadIdx.x == 0) {
        unsigned gen = g_bar_gen;
        __threadfence();
        if (atomicAdd(&g_bar_cnt, 1) == nCTA - 1) {
            g_bar_cnt = 0;
            __threadfence();
            g_bar_gen = gen + 1;
        } else {
            while (g_bar_gen == gen) { }
        }
        __threadfence();
    }
    __syncthreads();
}

// ---------------------------------------------------------------------------
__global__ void gather_emb_kernel(const int* __restrict__ dec,
                                  const float* __restrict__ emb,
                                  float* __restrict__ out) {
    int r = blockIdx.x;          // r = t*64 + b
    int t = r >> 6, b = r & 63;
    int tok = dec[b * TOUT + t];
    const float* src = emb + (size_t)tok * EMB;
    float* dst = out + (size_t)r * EMBP;
    for (int e = threadIdx.x; e < EMBP; e += blockDim.x)
        dst[e] = (e < EMB) ? src[e] : 0.f;
}

// ---------------------------------------------------------------------------
// mega_convert (R13 layout, Wfc included):
//  P0 [0,256) Wm | P1 [256,896) Wk0 | P2 [896,1920) Wk' | P3 [1920,2176) Wq fp16
//  P4 [2176,3200) Uk interleaved | P5 [3200,3712) Wa | P6 [3712,20736) Wfc fp16
__global__ void mega_convert_kernel(const float* __restrict__ Wm,
                                    const float* __restrict__ Wk,
                                    const float* __restrict__ Uk,
                                    const float* __restrict__ Wq,
                                    const float* __restrict__ Wa,
                                    const float* __restrict__ Wfc,
                                    __nv_bfloat16* __restrict__ wmT_h,
                                    __nv_bfloat16* __restrict__ wmT_l,
                                    __nv_bfloat16* __restrict__ wk0T_h,
                                    __nv_bfloat16* __restrict__ wk0T_l,
                                    __nv_bfloat16* __restrict__ wkpT_h,
                                    __nv_bfloat16* __restrict__ wkpT_l,
                                    __half* __restrict__ wqKh,
                                    __nv_bfloat16* __restrict__ uk0H,
                                    __nv_bfloat16* __restrict__ uk0L,
                                    __nv_bfloat16* __restrict__ waT_h,
                                    __nv_bfloat16* __restrict__ waT_l,
                                    __half* __restrict__ wT_h)
{
    __shared__ float tile[32][33];
    int bid = blockIdx.x;
    int tx = threadIdx.x & 31, ty = threadIdx.x >> 5;

    if (bid >= 1920 && bid < 2176) {     // P3: Wq straight fp16 copy
        int base = (bid - 1920) * 1024;
        for (int e = threadIdx.x; e < 1024; e += 256)
            wqKh[base + e] = __float2half_rn(Wq[base + e]);
        return;
    }
    if (bid >= 3712) {                   // P6: Wfc fp16 transpose
        int i = bid - 3712;
        int n0 = (i % 1064) * 32, k0 = (i / 1064) * 32;
        for (int j = ty; j < 32; j += 8) {
            int n = n0 + tx;
            tile[j][tx] = (n < VOCAB) ? Wfc[(size_t)(k0 + j) * VOCAB + n] : 0.f;
        }
        __syncthreads();
        for (int j = ty; j < 32; j += 8)
            wT_h[(size_t)(n0 + j) * UNITS + k0 + tx] = __float2half_rn(tile[tx][j]);
        return;
    }

    const float* W; int K, N, ldn, Kpad, mode, n0, k0;
    __nv_bfloat16 *hi, *lo;
    if (bid < 256) {
        int i = bid; W = Wm; K = 512; N = 512; ldn = 512; Kpad = 512; mode = 0;
        hi = wmT_h; lo = wmT_l; n0 = (i % 16) * 32; k0 = (i / 16) * 32;
    } else if (bid < 896) {
        int i = bid - 256; W = Wk; K = EMB; N = 2048; ldn = 2048; Kpad = EMBP; mode = 0;
        hi = wk0T_h; lo = wk0T_l; n0 = (i % 64) * 32; k0 = (i / 64) * 32;
    } else if (bid < 1920) {
        int i = bid - 896; W = Wk + (size_t)EMB * 2048; K = 512; N = 2048;
        ldn = 2048; Kpad = 512; mode = 0;
        hi = wkpT_h; lo = wkpT_l; n0 = (i % 64) * 32; k0 = (i / 64) * 32;
    } else if (bid < 3200) {
        int i = bid - 2176; W = Uk; K = 512; N = 2048; ldn = 2048; Kpad = 512; mode = 2;
        hi = uk0H; lo = uk0L; n0 = (i % 64) * 32; k0 = (i / 64) * 32;
    } else {
        int i = bid - 3200; W = Wa; K = 1024; N = 512; ldn = 512; Kpad = 1024; mode = 0;
        hi = waT_h; lo = waT_l; n0 = (i % 16) * 32; k0 = (i / 16) * 32;
    }

    for (int j = ty; j < 32; j += 8) {
        int k = k0 + j, n = n0 + tx;
        tile[j][tx] = (k < K && n < N) ? W[(size_t)k * ldn + n] : 0.f;
    }
    __syncthreads();
    for (int j = ty; j < 32; j += 8) {
        int n = n0 + j, k = k0 + tx;
        float v = tile[tx][j];
        int nn = (mode == 2) ? ((n & 511) * 4 + (n >> 9)) : n;
        __nv_bfloat16 h = __float2bfloat16(v);
        hi[(size_t)nn * Kpad + k] = h;
        lo[(size_t)nn * Kpad + k] = __float2bfloat16(v - __bfloat162float(h));
    }
}

// ---------------------------------------------------------------------------
// Core split-bf16 3-term mma GEMM (fp32 A on the fly, pre-split B).
#define FTS     72
#define F_ARR   (128 * FTS * 2)
#define F_STAGE (4 * F_ARR)
#define F_SMEM  (2 * F_STAGE)

template<int MODE>
__device__ __forceinline__ void gemm_core(
    char* dsm, int m0, int n0,
    const float* __restrict__ A, int lda, int M, int N, int K,
    const __nv_bfloat16* __restrict__ BhT,
    const __nv_bfloat16* __restrict__ BlT,
    const float* __restrict__ bias,
    float* __restrict__ C, int ldc,
    __half* __restrict__ Ch,
    __nv_bfloat16* __restrict__ OH, __nv_bfloat16* __restrict__ OL)
{
    const int tid  = threadIdx.x;
    const int wid  = tid >> 5, lane = tid & 31;
    const int wm   = wid & 1,  wn   = wid >> 1;
    const int mbase = wm * 64, nbase = wn * 32;
    const uint32_t sb = smem_u32(dsm);
    const int NIT = K >> 6;

    float acc[16][4];
#pragma unroll
    for (int i = 0; i < 16; i++)
#pragma unroll
        for (int j = 0; j < 4; j++) acc[i][j] = 0.f;

    float4 Areg[8];
    auto loadA = [&](int it) {
        int koff = it * 64;
#pragma unroll
        for (int l = 0; l < 8; l++) {
            int q = tid + l * 256;
            int r = q >> 4, c4 = (q & 15) * 4;
            int gm = m0 + r;
            Areg[l] = (gm < M) ? *(const float4*)(A + (size_t)gm * lda + koff + c4)
                               : make_float4(0.f, 0.f, 0.f, 0.f);
        }
    };
    auto storeA = [&](int stage) {
#pragma unroll
        for (int l = 0; l < 8; l++) {
            int q = tid + l * 256;
            int r = q >> 4, c4 = (q & 15) * 4;
            float4 v = Areg[l];
            uint32_t off = (uint32_t)(r * FTS + c4) * 2;
            uint2 hi = make_uint2(pack_bf2(v.x, v.y), pack_bf2(v.z, v.w));
            uint2 lo = make_uint2(pack_bf2(bf_res(v.x), bf_res(v.y)),
                                  pack_bf2(bf_res(v.z), bf_res(v.w)));
            *(uint2*)(dsm + stage * F_STAGE + 0 * F_ARR + off) = hi;
            *(uint2*)(dsm + stage * F_STAGE + 1 * F_ARR + off) = lo;
        }
    };
    auto issueB = [&](int it, int stage) {
        int koff = it * 64;
#pragma unroll
        for (int arr = 0; arr < 2; arr++) {
            const __nv_bfloat16* src = arr ? BlT : BhT;
#pragma unroll
            for (int l = 0; l < 4; l++) {
                int q = tid + l * 256;
                int r = q >> 3, c8 = (q & 7) * 8;
                uint32_t dst = sb + stage * F_STAGE + (2 + arr) * F_ARR
                             + (uint32_t)(r * FTS + c8) * 2;
                cp_async16(dst, src + (size_t)(n0 + r) * K + koff + c8);
            }
        }
        cp_commit();
    };
    auto compute = [&](int stage) {
        uint32_t aHb = sb + stage * F_STAGE;
        uint32_t aLb = aHb + F_ARR;
        uint32_t bHb = aHb + 2 * F_ARR;
        uint32_t bLb = aHb + 3 * F_ARR;
#pragma unroll
        for (int ks = 0; ks < 4; ks++) {
            uint32_t a_off = (uint32_t)(((mbase + (lane & 15)) * FTS
                              + ks * 16 + (lane >> 4) * 8) * 2);
            uint32_t aH[4][4], aL[4][4];
#pragma unroll
            for (int i = 0; i < 4; i++) {
                uint32_t o = a_off + (uint32_t)(i * 16 * FTS * 2);
                ldm_x4(aH[i][0], aH[i][1], aH[i][2], aH[i][3], aHb + o);
                ldm_x4(aL[i][0], aL[i][1], aL[i][2], aL[i][3], aLb + o);
            }
            uint32_t b_off = (uint32_t)(((nbase + (lane & 7) + (lane >> 4) * 8) * FTS
                              + ks * 16 + ((lane >> 3) & 1) * 8) * 2);
            uint32_t bH[4][2], bL[4][2];
#pragma unroll
            for (int jp = 0; jp < 2; jp++) {
                uint32_t o = b_off + (uint32_t)(jp * 16 * FTS * 2);
                ldm_x4(bH[jp*2][0], bH[jp*2][1], bH[jp*2+1][0], bH[jp*2+1][1], bHb + o);
                ldm_x4(bL[jp*2][0], bL[jp*2][1], bL[jp*2+1][0], bL[jp*2+1][1], bLb + o);
            }
#pragma unroll
            for (int i = 0; i < 4; i++)
#pragma unroll
                for (int j = 0; j < 4; j++) {
                    mma_bf16(acc[i * 4 + j], aH[i], bH[j]);
                    mma_bf16(acc[i * 4 + j], aH[i], bL[j]);
                    mma_bf16(acc[i * 4 + j], aL[i], bH[j]);
                }
        }
    };

    loadA(0);
    issueB(0, 0);
    if (NIT > 1) issueB(1, 1);
    for (int it = 0; it < NIT; it++) {
        int stage = it & 1;
        if (it >= NIT - 2) cp_wait<0>(); else cp_wait<1>();
        storeA(stage);
        __syncthreads();
        if (it + 1 < NIT) loadA(it + 1);
        compute(stage);
        __syncthreads();
        if (it + 2 < NIT) issueB(it + 2, stage);
    }

#pragma unroll
    for (int i = 0; i < 4; i++) {
        int row0 = m0 + mbase + i * 16 + (lane >> 2);
#pragma unroll
        for (int j = 0; j < 4; j++) {
            int col = n0 + nbase + j * 8 + (lane & 3) * 2;
            if (col >= N) continue;
            const float* c = acc[i * 4 + j];
#pragma unroll
            for (int hrow = 0; hrow < 2; hrow++) {
                int gm = row0 + hrow * 8;
                if (gm >= M) continue;
                float v0 = c[hrow * 2 + 0], v1 = c[hrow * 2 + 1];
                if (MODE == 0) {
                    float b0 = bias ? bias[col] : 0.f;
                    float b1 = bias ? bias[col + 1] : 0.f;
                    C[(size_t)gm * ldc + col]     = v0 + b0;
                    C[(size_t)gm * ldc + col + 1] = v1 + b1;
                } else if (MODE == 1) {
                    Ch[(size_t)gm * ldc + col]     = __float2half_rn(v0);
                    Ch[(size_t)gm * ldc + col + 1] = __float2half_rn(v1);
                } else {   // MODE 3
                    if (gm < 512) {
                        v0 += bias[(size_t)gm * 2048 + col];
                        v1 += bias[(size_t)gm * 2048 + col + 1];
                    }
                    int np0 = (col & 511) * 4 + (col >> 9);
                    int np1 = ((col + 1) & 511) * 4 + ((col + 1) >> 9);
                    __nv_bfloat16 h0 = __float2bfloat16(v0);
                    __nv_bfloat16 h1 = __float2bfloat16(v1);
                    OH[(size_t)np0 * 1024 + gm] = h0;
                    OL[(size_t)np0 * 1024 + gm] =
                        __float2bfloat16(v0 - __bfloat162float(h0));
                    OH[(size_t)np1 * 1024 + gm] = h1;
                    OL[(size_t)np1 * 1024 + gm] =
                        __float2bfloat16(v1 - __bfloat162float(h1));
                }
            }
        }
    }
}

// gemm3: keys->fp16 (120) + zpre (256) + wbig (128).
__global__ void __launch_bounds__(256)
gemm3_kernel(const float* __restrict__ mem,
             const __nv_bfloat16* __restrict__ wmT_h,
             const __nv_bfloat16* __restrict__ wmT_l,
             __half* __restrict__ keysh,
             const float* __restrict__ embA,
             const __nv_bfloat16* __restrict__ wk0T_h,
             const __nv_bfloat16* __restrict__ wk0T_l,
             const float* __restrict__ bk,
             float* __restrict__ zpre,
             const float* __restrict__ Wa,
             const __nv_bfloat16* __restrict__ wkpT_h,
             const __nv_bfloat16* __restrict__ wkpT_l,
             const float* __restrict__ Uk,
             __nv_bfloat16* __restrict__ wkuH,
             __nv_bfloat16* __restrict__ wkuL)
{
    extern __shared__ char dsm[];
    int bid = blockIdx.x;
    if (bid < 120) {
        int m0 = (bid % 30) * 128, n0 = (bid / 30) * 128;
        gemm_core<1>(dsm, m0, n0, mem, UNITS, B64 * TIN, UNITS, UNITS,
                     wmT_h, wmT_l, nullptr, nullptr, UNITS, keysh,
                     nullptr, nullptr);
    } else if (bid < 376) {
        int p = bid - 120;
        int m0 = (p % 16) * 128, n0 = (p / 16) * 128;
        gemm_core<0>(dsm, m0, n0, embA, EMBP, ROWS, 2048, EMBP,
                     wk0T_h, wk0T_l, bk, zpre, 2048, nullptr,
                     nullptr, nullptr);
    } else {
        int p = bid - 376;
        int m0 = (p % 8) * 128, n0 = (p / 8) * 128;
        gemm_core<3>(dsm, m0, n0, Wa, UNITS, 1024, 2048, UNITS,
                     wkpT_h, wkpT_l, Uk, nullptr, 0, nullptr,
                     wkuH, wkuL);
    }
}

__global__ void __launch_bounds__(256)
gemm_states_kernel(const float* __restrict__ hctx,
                   const __nv_bfloat16* __restrict__ waT_h,
                   const __nv_bfloat16* __restrict__ waT_l,
                   __half* __restrict__ sA_h)
{
    extern __shared__ char dsm[];
    int m0 = blockIdx.x * 128, n0 = blockIdx.y * 128;
    gemm_core<1>(dsm, m0, n0, hctx, 1024, ROWS, UNITS, 1024,
                 waT_h, waT_l, nullptr, nullptr, UNITS, sA_h,
                 nullptr, nullptr);
}

// ---------------------------------------------------------------------------
// PERSISTENT step loop: 128 CTAs x 512 threads (R13 structure).
// Gates: 64m x 16n', BK=64, 3-stage, 3 per-term accumulators.
// Attention: CTAs 0..63, vectorized q-GEMV, ctx with 4 partials.
#define PTS     72
#define P_AH    0
#define P_AL    9216
#define P_BH    18432
#define P_BL    20736
#define P_STAGE 23040
#define P_SMEM  (3 * P_STAGE)    // 69120 B

__global__ void __launch_bounds__(512, 1)
step_loop_kernel(const float* __restrict__ h0,
                 const float* __restrict__ c0,
                 const __nv_bfloat16* __restrict__ uk0H,
                 const __nv_bfloat16* __restrict__ uk0L,
                 const __nv_bfloat16* __restrict__ wkuH,
                 const __nv_bfloat16* __restrict__ wkuL,
                 const float* __restrict__ zpre,
                 float* __restrict__ cbuf,
                 float* __restrict__ hctx,
                 const __half* __restrict__ wqKh,   // [k][n]
                 const __half* __restrict__ keysh,
                 const float* __restrict__ memory,
                 const float* __restrict__ v_att)
{
    extern __shared__ char dsm[];
    const int cta  = blockIdx.x;              // 0..127
    const int tid  = threadIdx.x;
    const int wid  = tid >> 5, lane = tid & 31;
    const int mbase = (wid & 3) * 16;
    const int nbase = (wid >> 2) * 8;
    const int n0   = cta * 16;
    const uint32_t sb = smem_u32(dsm);
    const int nCTA = gridDim.x;

    for (int t = 0; t < TOUT; t++) {
        // ================= gates phase =================
        const float* Aptr; int astride, K;
        const __nv_bfloat16 *BH, *BL;
        if (t == 0) { Aptr = h0; astride = UNITS; K = 512; BH = uk0H; BL = uk0L; }
        else { Aptr = hctx + (size_t)(t - 1) * 1024; astride = HLD; K = 1024;
               BH = wkuH; BL = wkuL; }
        const float* cprev = t ? (cbuf + (size_t)((t - 1) & 1) * B64 * UNITS) : c0;
        float* cnew = cbuf + (size_t)(t & 1) * B64 * UNITS;
        const int NIT = K >> 6;

        float accT[3][4];
#pragma unroll
        for (int j = 0; j < 3; j++)
#pragma unroll
            for (int e = 0; e < 4; e++) accT[j][e] = 0.f;
        float4 Areg[2];

        auto issueB = [&](int it, int stage) {
            int koff = it * 64;
            if (tid < 256) {
                int arr = tid >> 7;
                int rem = tid & 127;
                int r   = rem >> 3;
                int c8  = (rem & 7) * 8;
                const __nv_bfloat16* src = arr ? BL : BH;
                uint32_t dst = sb + stage * P_STAGE + (arr ? P_BL : P_BH)
                             + (uint32_t)(r * PTS + c8) * 2;
                cp_async16(dst, src + (size_t)(n0 + r) * K + koff + c8);
            }
            cp_commit();
        };
        auto loadA = [&](int it) {
            int koff = it * 64;
#pragma unroll
            for (int l = 0; l < 2; l++) {
                int q = tid + l * 512;
                int r = q >> 4, c4 = (q & 15) * 4;
                Areg[l] = *(const float4*)(Aptr + (size_t)r * astride + koff + c4);
            }
        };
        auto storeA = [&](int stage) {
#pragma unroll
            for (int l = 0; l < 2; l++) {
                int q = tid + l * 512;
                int r = q >> 4, c4 = (q & 15) * 4;
                float4 v = Areg[l];
                uint32_t off = (uint32_t)(r * PTS + c4) * 2;
                uint2 hi = make_uint2(pack_bf2(v.x, v.y), pack_bf2(v.z, v.w));
                uint2 lo = make_uint2(pack_bf2(bf_res(v.x), bf_res(v.y)),
                                      pack_bf2(bf_res(v.z), bf_res(v.w)));
                *(uint2*)(dsm + stage * P_STAGE + P_AH + off) = hi;
                *(uint2*)(dsm + stage * P_STAGE + P_AL + off) = lo;
            }
        };
        auto compute = [&](int stage) {
            uint32_t aHb = sb + stage * P_STAGE + P_AH;
            uint32_t aLb = sb + stage * P_STAGE + P_AL;
            uint32_t bHb = sb + stage * P_STAGE + P_BH;
            uint32_t bLb = sb + stage * P_STAGE + P_BL;
#pragma unroll
            for (int ks = 0; ks < 4; ks++) {
                uint32_t a_off = (uint32_t)(((mbase + (lane & 15)) * PTS
                                  + ks * 16 + (lane >> 4) * 8) * 2);
                uint32_t aH[4], aL[4];
                ldm_x4(aH[0], aH[1], aH[2], aH[3], aHb + a_off);
                ldm_x4(aL[0], aL[1], aL[2], aL[3], aLb + a_off);
                uint32_t b_off = (uint32_t)(((nbase + (lane & 7)) * PTS
                                  + ks * 16 + ((lane >> 3) & 1) * 8) * 2);
                uint32_t bH[2], bL[2];
                ldm_x2(bH[0], bH[1], bHb + b_off);
                ldm_x2(bL[0], bL[1], bLb + b_off);
                mma_bf16(accT[0], aH, bH);     // 3 independent chains
                mma_bf16(accT[1], aH, bL);
                mma_bf16(accT[2], aL, bH);
            }
        };

        loadA(0);
        issueB(0, 0);
        issueB(1, 1);
        issueB(2, 2);
        for (int it = 0; it < NIT; it++) {
            int stage = it % 3;
            if (it + 3 <= NIT)      cp_wait<2>();
            else if (it + 2 == NIT) cp_wait<1>();
            else                    cp_wait<0>();
            storeA(stage);
            __syncthreads();
            if (it + 1 < NIT) loadA(it + 1);
            if (wid < 8) compute(stage);
            __syncthreads();
            if (it + 3 < NIT) issueB(it + 3, stage);
        }

        // ---- LSTM epilogue ----
        float* zbuf = (float*)dsm;               // [64][20]
        if (wid < 8) {
            int row = mbase + (lane >> 2);
            int col = nbase + (lane & 3) * 2;
            zbuf[row * 20 + col]           = accT[0][0] + accT[1][0] + accT[2][0];
            zbuf[row * 20 + col + 1]       = accT[0][1] + accT[1][1] + accT[2][1];
            zbuf[(row + 8) * 20 + col]     = accT[0][2] + accT[1][2] + accT[2][2];
            zbuf[(row + 8) * 20 + col + 1] = accT[0][3] + accT[1][3] + accT[2][3];
        }
        __syncthreads();
        if (tid < 256) {
            int b  = tid >> 2, ul = tid & 3;
            int u  = cta * 4 + ul;
            const float* ad = zpre + (size_t)t * B64 * 2048 + (size_t)b * 2048;
            float zi = zbuf[b * 20 + ul * 4 + 0] + ad[u];
            float zf = zbuf[b * 20 + ul * 4 + 1] + ad[512 + u];
            float zg = zbuf[b * 20 + ul * 4 + 2] + ad[1024 + u];
            float zo = zbuf[b * 20 + ul * 4 + 3] + ad[1536 + u];
            float si = fast_sigmoid(zi);
            float sf = fast_sigmoid(zf);
            float so = fast_sigmoid(zo);
            float tg = fast_tanh(zg);
            float c  = sf * cprev[(size_t)b * UNITS + u] + si * tg;
            float h  = so * fast_tanh(c);
            cnew[(size_t)b * UNITS + u] = c;
            hctx[(size_t)b * HLD + (size_t)t * 1024 + u] = h;
        }

        grid_barrier(nCTA);

        // ================= attention phase (CTAs 0..63) =================
        if (cta < B64) {
            int b = cta;
            float* sh    = (float*)dsm;            // 512
            float* sq    = sh + 512;               // 512
            float* ssc   = sq + 512;               // 64
            float* qpart = ssc + 64;               // 8 x 512
            float* hrow = hctx + (size_t)b * HLD + (size_t)t * 1024;

            sh[tid] = hrow[tid];
            __syncthreads();
            {   // q-GEMV vectorized (uint4, 8 k-slices)
                int kslice = tid >> 6;
                int n8 = (tid & 63) * 8;
                float a[8];
#pragma unroll
                for (int j = 0; j < 8; j++) a[j] = 0.f;
                const __half* wp = wqKh + (size_t)(kslice * 64) * UNITS + n8;
                const float* shk = sh + kslice * 64;
#pragma unroll 4
                for (int k = 0; k < 64; k++) {
                    float hk = shk[k];
                    uint4 raw = *(const uint4*)(wp + (size_t)k * UNITS);
                    float2 f0 = __half22float2(*(__half2*)&raw.x);
                    float2 f1 = __half22float2(*(__half2*)&raw.y);
                    float2 f2 = __half22float2(*(__half2*)&raw.z);
                    float2 f3 = __half22float2(*(__half2*)&raw.w);
                    a[0] = fmaf(hk, f0.x, a[0]);
                    a[1] = fmaf(hk, f0.y, a[1]);
                    a[2] = fmaf(hk, f1.x, a[2]);
                    a[3] = fmaf(hk, f1.y, a[3]);
                    a[4] = fmaf(hk, f2.x, a[4]);
                    a[5] = fmaf(hk, f2.y, a[5]);
                    a[6] = fmaf(hk, f3.x, a[6]);
                    a[7] = fmaf(hk, f3.y, a[7]);
                }
                float* qp = qpart + kslice * 512 + n8;
#pragma unroll
                for (int j = 0; j < 8; j++) qp[j] = a[j];
            }
            __syncthreads();
            {
                float s = 0.f;
#pragma unroll
                for (int sl = 0; sl < 8; sl++) s += qpart[sl * 512 + tid];
                sq[tid] = s;
            }
            __syncthreads();

            for (int s = wid; s < TIN; s += 16) {
                const __half* krow = keysh + ((size_t)b * TIN + s) * UNITS;
                float sc = 0.f;
#pragma unroll 4
                for (int u = lane; u < UNITS; u += 32)
                    sc += fast_tanh(__half2float(krow[u]) + sq[u]) * v_att[u];
#pragma unroll
                for (int off = 16; off; off >>= 1)
                    sc += __shfl_xor_sync(~0u, sc, off);
                if (lane == 0) ssc[s] = sc;
            }
            __syncthreads();

            if (tid < 32) {
                float m = -1e30f;
                for (int s = lane; s < TIN; s += 32) m = fmaxf(m, ssc[s]);
#pragma unroll
                for (int off = 16; off; off >>= 1)
                    m = fmaxf(m, __shfl_xor_sync(~0u, m, off));
                float ssum = 0.f;
                for (int s = lane; s < TIN; s += 32) {
                    float e = __expf(ssc[s] - m);
                    ssc[s] = e; ssum += e;
                }
#pragma unroll
                for (int off = 16; off; off >>= 1)
                    ssum += __shfl_xor_sync(~0u, ssum, off);
                float inv = __fdividef(1.f, ssum);
                for (int s = lane; s < TIN; s += 32) ssc[s] *= inv;
            }
            __syncthreads();

            const float* mrow = memory + (size_t)b * TIN * UNITS;
            float p0 = 0.f, p1 = 0.f, p2 = 0.f, p3 = 0.f;
#pragma unroll
            for (int s = 0; s < TIN; s += 4) {
                p0 = fmaf(ssc[s + 0], mrow[(size_t)(s + 0) * UNITS + tid], p0);
                p1 = fmaf(ssc[s + 1], mrow[(size_t)(s + 1) * UNITS + tid], p1);
                p2 = fmaf(ssc[s + 2], mrow[(size_t)(s + 2) * UNITS + tid], p2);
                p3 = fmaf(ssc[s + 3], mrow[(size_t)(s + 3) * UNITS + tid], p3);
            }
            hrow[512 + tid] = (p0 + p1) + (p2 + p3);
        }

        grid_barrier(nCTA);
    }
}

// ---------------------------------------------------------------------------
// Vocab GEMM: 1-term fp16.
#define V_ARR   (128 * FTS * 2)
#define V_STAGE (2 * V_ARR)
#define V_SMEM  (2 * V_STAGE)

__global__ void __launch_bounds__(256)
gemm_vocab_f16(const __half* __restrict__ Ah,
               const __half* __restrict__ Bh,
               const float* __restrict__ bias,
               float* __restrict__ out)
{
    extern __shared__ char dsm[];
    const int m0 = blockIdx.x * 128;
    const int n0 = blockIdx.y * 128;
    const int tid  = threadIdx.x;
    const int wid  = tid >> 5, lane = tid & 31;
    const int wm   = wid & 1,  wn   = wid >> 1;
    const int mbase = wm * 64, nbase = wn * 32;
    const uint32_t sb = smem_u32(dsm);

    float acc[16][4];
#pragma unroll
    for (int i = 0; i < 16; i++)
#pragma unroll
        for (int j = 0; j < 4; j++) acc[i][j] = 0.f;

    auto issue = [&](int it, int stage) {
        int koff = it * 64;
#pragma unroll
        for (int arr = 0; arr < 2; arr++) {
            const __half* src = arr ? Bh : Ah;
            const int rbase = arr ? n0 : m0;
#pragma unroll
            for (int l = 0; l < 4; l++) {
                int q = tid + l * 256;
                int r = q >> 3, c8 = (q & 7) * 8;
                uint32_t dst = sb + stage * V_STAGE + arr * V_ARR
                             + (uint32_t)(r * FTS + c8) * 2;
                cp_async16(dst, src + (size_t)(rbase + r) * UNITS + koff + c8);
            }
        }
        cp_commit();
    };
    auto compute = [&](int stage) {
        uint32_t aHb = sb + stage * V_STAGE;
        uint32_t bHb = aHb + V_ARR;
#pragma unroll
        for (int ks = 0; ks < 4; ks++) {
            uint32_t a_off = (uint32_t)(((mbase + (lane & 15)) * FTS
                              + ks * 16 + (lane >> 4) * 8) * 2);
            uint32_t aH[4][4];
#pragma unroll
            for (int i = 0; i < 4; i++) {
                uint32_t o = a_off + (uint32_t)(i * 16 * FTS * 2);
                ldm_x4(aH[i][0], aH[i][1], aH[i][2], aH[i][3], aHb + o);
            }
            uint32_t b_off = (uint32_t)(((nbase + (lane & 7) + (lane >> 4) * 8) * FTS
                              + ks * 16 + ((lane >> 3) & 1) * 8) * 2);
            uint32_t bH[4][2];
#pragma unroll
            for (int jp = 0; jp < 2; jp++) {
                uint32_t o = b_off + (uint32_t)(jp * 16 * FTS * 2);
                ldm_x4(bH[jp*2][0], bH[jp*2][1], bH[jp*2+1][0], bH[jp*2+1][1], bHb + o);
            }
#pragma unroll
            for (int i = 0; i < 4; i++)
#pragma unroll
                for (int j = 0; j < 4; j++)
                    mma_f16(acc[i * 4 + j], aH[i], bH[j]);
        }
    };

    issue(0, 0);
    issue(1, 1);
    for (int it = 0; it < 8; it++) {
        int stage = it & 1;
        if (it >= 6) cp_wait<0>(); else cp_wait<1>();
        __syncthreads();
        compute(stage);
        __syncthreads();
        if (it + 2 < 8) issue(it + 2, stage);
    }

#pragma unroll
    for (int i = 0; i < 4; i++) {
        int row0 = m0 + mbase + i * 16 + (lane >> 2);
#pragma unroll
        for (int j = 0; j < 4; j++) {
            int col = n0 + nbase + j * 8 + (lane & 3) * 2;
            if (col >= VOCAB) continue;
            float b0 = bias[col], b1 = bias[col + 1];
            const float* c = acc[i * 4 + j];
            if (row0 < ROWS) {
                out[(size_t)row0 * VOCAB + col]     = c[0] + b0;
                out[(size_t)row0 * VOCAB + col + 1] = c[1] + b1;
            }
            if (row0 + 8 < ROWS) {
                out[(size_t)(row0 + 8) * VOCAB + col]     = c[2] + b0;
                out[(size_t)(row0 + 8) * VOCAB + col + 1] = c[3] + b1;
            }
        }
    }
}

// ---------------------------------------------------------------------------
static inline float* sym_addr(const void* sym) {
    void* p = nullptr;
    cudaGetSymbolAddress(&p, sym);
    return (float*)p;
}
static inline __nv_bfloat16* sym_addr_bf(const void* sym) {
    void* p = nullptr;
    cudaGetSymbolAddress(&p, sym);
    return (__nv_bfloat16*)p;
}
static inline __half* sym_addr_h(const void* sym) {
    void* p = nullptr;
    cudaGetSymbolAddress(&p, sym);
    return (__half*)p;
}

extern "C" void kernel_launch(void* const* d_in, const int* in_sizes, int n_in,
                              void* d_out, int out_size)
{
    const int*   dec = (const int*)  d_in[0];
    const float* h0  = (const float*)d_in[1];
    const float* c0  = (const float*)d_in[2];
    const float* mem = (const float*)d_in[3];
    const float* emb = (const float*)d_in[4];
    const float* Wk  = (const float*)d_in[5];
    const float* Uk  = (const float*)d_in[6];
    const float* bk  = (const float*)d_in[7];
    const float* Wm  = (const float*)d_in[8];
    const float* Wq  = (const float*)d_in[9];
    const float* vat = (const float*)d_in[10];
    const float* Wa  = (const float*)d_in[11];
    const float* Wfc = (const float*)d_in[12];
    const float* bfc = (const float*)d_in[13];
    float* out = (float*)d_out;

    float* embA   = sym_addr(g_embA);
    float* zpre   = sym_addr(g_zpre);
    float* cbuf   = sym_addr(g_cbuf);
    float* hctx   = sym_addr(g_hctx);
    __half* keysh = sym_addr_h(g_keysh);
    __half* wqKh  = sym_addr_h(g_wqKh);
    __half* sA_h  = sym_addr_h(g_sA_h);
    __half* wT_h  = sym_addr_h(g_wT_h);
    __nv_bfloat16* wkuH = sym_addr_bf(g_wkuH);
    __nv_bfloat16* wkuL = sym_addr_bf(g_wkuL);
    __nv_bfloat16* uk0H = sym_addr_bf(g_uk0H);
    __nv_bfloat16* uk0L = sym_addr_bf(g_uk0L);
    __nv_bfloat16* wmT_h  = sym_addr_bf(g_wmT_h);
    __nv_bfloat16* wmT_l  = sym_addr_bf(g_wmT_l);
    __nv_bfloat16* wk0T_h = sym_addr_bf(g_wk0T_h);
    __nv_bfloat16* wk0T_l = sym_addr_bf(g_wk0T_l);
    __nv_bfloat16* wkpT_h = sym_addr_bf(g_wkpT_h);
    __nv_bfloat16* wkpT_l = sym_addr_bf(g_wkpT_l);
    __nv_bfloat16* waT_h  = sym_addr_bf(g_waT_h);
    __nv_bfloat16* waT_l  = sym_addr_bf(g_waT_l);

    cudaFuncSetAttribute(gemm3_kernel,
                         cudaFuncAttributeMaxDynamicSharedMemorySize, F_SMEM);
    cudaFuncSetAttribute(gemm_states_kernel,
                         cudaFuncAttributeMaxDynamicSharedMemorySize, F_SMEM);
    cudaFuncSetAttribute(step_loop_kernel,
                         cudaFuncAttributeMaxDynamicSharedMemorySize, P_SMEM);
    cudaFuncSetAttribute(gemm_vocab_f16,
                         cudaFuncAttributeMaxDynamicSharedMemorySize, V_SMEM);

    // 1: gather
    gather_emb_kernel<<<ROWS, 128>>>(dec, emb, embA);
    // 2: all weight converts (incl Wfc)
    mega_convert_kernel<<<20736, 256>>>(Wm, Wk, Uk, Wq, Wa, Wfc,
                                        wmT_h, wmT_l, wk0T_h, wk0T_l,
                                        wkpT_h, wkpT_l, wqKh, uk0H, uk0L,
                                        waT_h, waT_l, wT_h);
    // 3: keys(fp16) + zpre + wbig
    gemm3_kernel<<<504, 256, F_SMEM>>>(mem, wmT_h, wmT_l, keysh,
                                       embA, wk0T_h, wk0T_l, bk, zpre,
                                       Wa, wkpT_h, wkpT_l, Uk, wkuH, wkuL);
    // 4: persistent step loop (128 CTAs)
    step_loop_kernel<<<128, 512, P_SMEM>>>(
        h0, c0, uk0H, uk0L, wkuH, wkuL, zpre, cbuf, hctx,
        wqKh, keysh, mem, vat);
    // 5: states = hctx @ Wa -> fp16
    gemm_states_kernel<<<dim3(16, 4), 256, F_SMEM>>>(hctx, waT_h, waT_l, sA_h);
    // 6: vocab projection
    gemm_vocab_f16<<<dim3(MPAD / 128, VPAD / 128), 256, V_SMEM>>>(
        sA_h, wT_h, bfc, out);
}